// round 9
// baseline (speedup 1.0000x reference)
#include <cuda_runtime.h>
#include <math.h>
#include <stdint.h>

#define BATCH 65536
#define D0 784
#define D1 512
#define D2 256
#define D3 10
#define KP1 800            // 784 padded to 25*32 (B planes only)
#define KP2 512
#define K_DESC 32768
#define R_ASC (BATCH - 1 - K_DESC)   // 32767

#define TILE_M 128
#define TILE_N 128
#define CHUNK 32           // K floats per chunk = 128B rows (SW128 atom width)
#define NSTAGE 3

// Does this compilation pass support tcgen05 (arch-specific sm_103a/sm_100a)?
#if defined(__CUDA_ARCH__) && (defined(__CUDA_ARCH_FEAT_SM103_ALL) || \
                               defined(__CUDA_ARCH_FEAT_SM100_ALL) || \
                               defined(__CUDA_ARCH_SPECIFIC__)     || \
                               defined(__CUDA_ARCH_FAMILY_SPECIFIC__))
#define USE_TC 1
#else
#define USE_TC 0
#endif

// tf32 SS MMA idesc: dtype=F32(1<<4), atype=TF32(2<<7), btype=TF32(2<<10),
// N field = (N/4)<<16, M field = (M/16)<<24
#define IDESC_TF32 ((1u<<4)|(2u<<7)|(2u<<10)|((128u/4)<<16)|((128u/16)<<24))

// SW128 smem descriptor base (layout=2, version=1, SBO=64, LBO=1)
#define DESC_BASE ((2ull<<61)|(1ull<<46)|(64ull<<32)|(1ull<<16))

// smem layout: [0..8) tmem ptr, [8..32) mbars, [1024..1536) bias, stages at 2048
#define SM_BIAS  1024
#define SM_STAGE 2048
#define STAGE_BYTES 65536          // Ah 16K | Al 16K | Bh 16K | Bl 16K
#define OFF_AL 16384
#define OFF_BH 32768
#define OFF_BL 49152
#define GEMM_SMEM (SM_STAGE + NSTAGE * STAGE_BYTES)

// ---------------- scratch -----------------------------------------------------
__device__ float g_h1[(size_t)BATCH * D1];
__device__ float g_h2[(size_t)BATCH * D2];
__device__ float g_h3[(size_t)BATCH * D3];
__device__ float g_h4[(size_t)BATCH * D3];
__device__ float g_norm[BATCH];
__device__ float g_mask1[BATCH];
__device__ float g_mask2[BATCH];
__device__ float g_mask3[BATCH];
__device__ float g_part[4 * BATCH];
__device__ float g_w1hT[(size_t)D1 * KP1];
__device__ float g_w1lT[(size_t)D1 * KP1];
__device__ float g_w2hT[(size_t)D2 * KP2];
__device__ float g_w2lT[(size_t)D2 * KP2];
__device__ unsigned g_hist[4][65536];
__device__ float g_thr[1];

// ---------------- helpers (safe on all targets) -------------------------------
__device__ __forceinline__ uint32_t smem_u32(const void* p) {
    uint32_t a;
    asm("{ .reg .u64 t; cvta.to.shared.u64 t, %1; cvt.u32.u64 %0, t; }" : "=r"(a) : "l"(p));
    return a;
}
__device__ __forceinline__ float trunc_tf32(float v) {
    return __uint_as_float(__float_as_uint(v) & 0xffffe000u);
}

#if USE_TC
__device__ __forceinline__ void cp16(uint32_t dst, const void* src) {
    asm volatile("cp.async.cg.shared.global [%0], [%1], 16;"
                 :: "r"(dst), "l"(src) : "memory");
}
__device__ __forceinline__ void cp_commit() {
    asm volatile("cp.async.commit_group;" ::: "memory");
}
__device__ __forceinline__ void cp_wait1() {
    asm volatile("cp.async.wait_group 1;" ::: "memory");
}
__device__ __forceinline__ void cp_wait0() {
    asm volatile("cp.async.wait_group 0;" ::: "memory");
}
__device__ __forceinline__ void sts128(uint32_t addr, float4 v) {
    asm volatile("st.shared.v4.f32 [%0], {%1,%2,%3,%4};"
                 :: "r"(addr), "f"(v.x), "f"(v.y), "f"(v.z), "f"(v.w) : "memory");
}
__device__ __forceinline__ void mbar_init(uint32_t addr) {
    asm volatile("mbarrier.init.shared.b64 [%0], 1;" :: "r"(addr) : "memory");
}
__device__ __forceinline__ void mbar_inval(uint32_t addr) {
    asm volatile("mbarrier.inval.shared.b64 [%0];" :: "r"(addr) : "memory");
}
__device__ __forceinline__ void mbar_wait(uint32_t addr, int parity) {
    asm volatile(
        "{\n\t.reg .pred P;\n"
        "WL_%=:\n\t"
        "mbarrier.try_wait.parity.acquire.cta.shared::cta.b64 P, [%0], %1, 0x989680;\n\t"
        "@P bra.uni WD_%=;\n\t"
        "bra.uni WL_%=;\n"
        "WD_%=:\n\t}"
        :: "r"(addr), "r"(parity) : "memory");
}
__device__ __forceinline__ void tmem_alloc(uint32_t smem_dst, uint32_t ncols) {
    asm volatile("tcgen05.alloc.cta_group::1.sync.aligned.shared::cta.b32 [%0], %1;"
                 :: "r"(smem_dst), "r"(ncols) : "memory");
}
__device__ __forceinline__ void tmem_dealloc(uint32_t tmem, uint32_t ncols) {
    asm volatile("tcgen05.relinquish_alloc_permit.cta_group::1.sync.aligned;");
    asm volatile("tcgen05.dealloc.cta_group::1.sync.aligned.b32 %0, %1;" :: "r"(tmem), "r"(ncols));
}
__device__ __forceinline__ void mma_tf32(uint32_t d, uint64_t ad, uint64_t bd, bool accum) {
    uint32_t en = accum ? 1u : 0u;
    asm volatile(
        "{\n\t.reg .pred p;\n\t"
        "setp.ne.u32 p, %4, 0;\n\t"
        "tcgen05.mma.cta_group::1.kind::tf32 [%0], %1, %2, %3, {%5,%5,%5,%5}, p;\n\t}"
        :: "r"(d), "l"(ad), "l"(bd), "r"(IDESC_TF32), "r"(en), "r"(0u) : "memory");
}
__device__ __forceinline__ void mma_commit(uint32_t mbar) {
    asm volatile("tcgen05.commit.cta_group::1.mbarrier::arrive::one.shared::cluster.b64 [%0];"
                 :: "r"(mbar) : "memory");
}
#define LDTM_X32(r, addr) \
    asm volatile( \
        "tcgen05.ld.sync.aligned.32x32b.x32.b32 " \
        "{%0, %1, %2, %3, %4, %5, %6, %7, " \
        " %8, %9, %10, %11, %12, %13, %14, %15, " \
        " %16, %17, %18, %19, %20, %21, %22, %23, " \
        " %24, %25, %26, %27, %28, %29, %30, %31}, [%32];" \
        : "=r"((r)[0]),  "=r"((r)[1]),  "=r"((r)[2]),  "=r"((r)[3]), \
          "=r"((r)[4]),  "=r"((r)[5]),  "=r"((r)[6]),  "=r"((r)[7]), \
          "=r"((r)[8]),  "=r"((r)[9]),  "=r"((r)[10]), "=r"((r)[11]), \
          "=r"((r)[12]), "=r"((r)[13]), "=r"((r)[14]), "=r"((r)[15]), \
          "=r"((r)[16]), "=r"((r)[17]), "=r"((r)[18]), "=r"((r)[19]), \
          "=r"((r)[20]), "=r"((r)[21]), "=r"((r)[22]), "=r"((r)[23]), \
          "=r"((r)[24]), "=r"((r)[25]), "=r"((r)[26]), "=r"((r)[27]), \
          "=r"((r)[28]), "=r"((r)[29]), "=r"((r)[30]), "=r"((r)[31]) \
        : "r"(addr))

__device__ __forceinline__ uint64_t mkdesc(uint32_t addr) {
    return DESC_BASE | ((uint64_t)(addr >> 4) & 0x3FFFull);
}
#endif  // USE_TC

// ---------------- weight transpose + tf32 split -------------------------------
__global__ void prep_split_T(const float* __restrict__ W, float* __restrict__ hiT,
                             float* __restrict__ loT, int K, int N, int KP) {
    int idx = blockIdx.x * blockDim.x + threadIdx.x;
    if (idx >= N * KP) return;
    int n = idx / KP, k = idx % KP;
    float v = (k < K) ? W[(size_t)k * N + n] : 0.0f;
    float h = trunc_tf32(v);
    hiT[idx] = h;
    loT[idx] = v - h;
}

__global__ void zero_hists_kernel(unsigned* h) {
    int i = blockIdx.x * blockDim.x + threadIdx.x;
    if (i < 4 * 65536) h[i] = 0u;
}

// ---------------- tcgen05 TF32 split-GEMM, 3-stage ring, early B issue --------
// C = relu(mask[m]*(A @ B^T) + bias). A raw fp32 [M, lda]; hi/lo split in regs
// (LDG issued one iteration ahead of STS). B^T pre-split planes staged via
// cp.async, issued one chunk ahead (wait_group 1). 3 TF32 products.
// Per-(n-block,row) sumsq partial into part[blockIdx.x*BATCH + m].
__global__ __launch_bounds__(256)
void gemm_tc(const float* __restrict__ A, const float* __restrict__ BhT,
             const float* __restrict__ BlT, const float* __restrict__ bias,
             const float* __restrict__ mask, float* __restrict__ C,
             float* __restrict__ part, int lda, int KP, int nchunks, int ldc) {
    extern __shared__ char smem[];
    const int tid = threadIdx.x;
    const int m0 = blockIdx.y * TILE_M;
    const int n0 = blockIdx.x * TILE_N;

#if USE_TC
    const uint32_t sb = smem_u32(smem);
    float* bias_s = reinterpret_cast<float*>(smem + SM_BIAS);
    if (tid == 0) { mbar_init(sb + 8); mbar_init(sb + 16); }
    if (tid < 32) tmem_alloc(sb, 128);
    if (tid < TILE_N) bias_s[tid] = bias[n0 + tid];
    __syncthreads();
    uint32_t tmem;
    asm volatile("ld.shared.b32 %0, [%1];" : "=r"(tmem) : "r"(sb));

    const int Klast = lda - 4;
    const int arow = tid >> 3;       // A: rows advance by 32 per it (4 its)
    const int aq = tid & 7;
    const float* Abase = A + (size_t)m0 * lda;
    const int brow = tid >> 2;       // B: 1024 units/plane: row = i>>3
    // B unit mapping: i = tid + it*256 (it<4); row = i>>3, q = i&7

    // prologue: LDG A(0); issue B(0) into stage 0
    float4 va[4];
    {
        const int kA = aq * 4;
#pragma unroll
        for (int it = 0; it < 4; it++) {
            const int row = arow + it * 32;
            va[it] = (kA <= Klast)
                ? *reinterpret_cast<const float4*>(Abase + (size_t)row * lda + kA)
                : make_float4(0.f, 0.f, 0.f, 0.f);
        }
        const uint32_t stb = sb + SM_STAGE;
#pragma unroll
        for (int it = 0; it < 4; it++) {
            const int i = tid + it * 256;
            const int row = i >> 3, q = i & 7;
            const uint32_t off = row * 128 + q * 16;
            const uint32_t swo = off ^ ((off >> 3) & 0x70);
            const size_t goff = (size_t)(n0 + row) * KP + q * 4;
            cp16(stb + OFF_BH + swo, BhT + goff);
            cp16(stb + OFF_BL + swo, BlT + goff);
        }
        cp_commit();
    }
    (void)brow;

    int ph0 = 0, ph1 = 0;
#pragma unroll 1
    for (int t = 0; t < nchunks; t++) {
        // LDG A(t+1) into vb (consumed next iteration)
        float4 vb[4];
        {
            const int tn = (t + 1 < nchunks) ? t + 1 : t;
            const int kA = tn * CHUNK + aq * 4;
#pragma unroll
            for (int it = 0; it < 4; it++) {
                const int row = arow + it * 32;
                vb[it] = (kA <= Klast)
                    ? *reinterpret_cast<const float4*>(Abase + (size_t)row * lda + kA)
                    : make_float4(0.f, 0.f, 0.f, 0.f);
            }
        }

        // wait MMA(t-2): frees stage (t+1)%3 for B and stage t%3 for A
        if (t >= 2) {
            if ((t & 1) == 0) { mbar_wait(sb + 8, ph0);  ph0 ^= 1; }
            else              { mbar_wait(sb + 16, ph1); ph1 ^= 1; }
        }

        // issue B(t+1) into stage (t+1)%3 (held chunk t-2, MMA done)
        if (t + 1 < nchunks) {
            const uint32_t stb = sb + SM_STAGE + ((t + 1) % NSTAGE) * STAGE_BYTES;
            const int kb = (t + 1) * CHUNK;
#pragma unroll
            for (int it = 0; it < 4; it++) {
                const int i = tid + it * 256;
                const int row = i >> 3, q = i & 7;
                const uint32_t off = row * 128 + q * 16;
                const uint32_t swo = off ^ ((off >> 3) & 0x70);
                const size_t goff = (size_t)(n0 + row) * KP + kb + q * 4;
                cp16(stb + OFF_BH + swo, BhT + goff);
                cp16(stb + OFF_BL + swo, BlT + goff);
            }
            cp_commit();
        }

        // split + STS A(t) into stage t%3 (held chunk t-3, MMA done)
        const uint32_t stb = sb + SM_STAGE + (t % NSTAGE) * STAGE_BYTES;
#pragma unroll
        for (int it = 0; it < 4; it++) {
            const int row = arow + it * 32;
            const uint32_t off = row * 128 + aq * 16;
            const uint32_t swo = off ^ ((off >> 3) & 0x70);
            float4 h, l;
            h.x = trunc_tf32(va[it].x); l.x = va[it].x - h.x;
            h.y = trunc_tf32(va[it].y); l.y = va[it].y - h.y;
            h.z = trunc_tf32(va[it].z); l.z = va[it].z - h.z;
            h.w = trunc_tf32(va[it].w); l.w = va[it].w - h.w;
            sts128(stb + swo, h);
            sts128(stb + OFF_AL + swo, l);
        }

        // B(t) (issued last iteration) must have arrived; only B(t+1) pending
        if (t + 1 < nchunks) cp_wait1(); else cp_wait0();
        asm volatile("fence.proxy.async.shared::cta;" ::: "memory");
        __syncthreads();

        if (tid == 0) {
            const uint64_t dah = mkdesc(stb);
            const uint64_t dal = mkdesc(stb + OFF_AL);
            const uint64_t dbh = mkdesc(stb + OFF_BH);
            const uint64_t dbl = mkdesc(stb + OFF_BL);
#pragma unroll
            for (int ks = 0; ks < 4; ks++) {
                const uint64_t o = ks * 2;
                mma_tf32(tmem, dah + o, dbh + o, !(t == 0 && ks == 0));
                mma_tf32(tmem, dah + o, dbl + o, true);
                mma_tf32(tmem, dal + o, dbh + o, true);
            }
            mma_commit(sb + 8 + 8 * (t & 1));
        }

#pragma unroll
        for (int it = 0; it < 4; it++) va[it] = vb[it];
    }
    // drain MMA(nchunks-1)
    {
        if (((nchunks - 1) & 1) == 0) mbar_wait(sb + 8, ph0);
        else                          mbar_wait(sb + 16, ph1);
    }
    asm volatile("tcgen05.fence::after_thread_sync;" ::: "memory");

    // epilogue: warps 0-3 read TMEM D (128 cols); bias+relu+mask, store, sumsq
    const int wid = tid >> 5, lane = tid & 31;
    if (wid < 4) {
        const int m = m0 + wid * 32 + lane;
        const float msk = mask ? mask[m] : 1.0f;
        float sumsq = 0.0f;
#pragma unroll 1
        for (int cc = 0; cc < 4; cc++) {
            uint32_t r[32];
            LDTM_X32(r, tmem + cc * 32);
            asm volatile("tcgen05.wait::ld.sync.aligned;" ::: "memory");
            float vals[32];
#pragma unroll
            for (int j = 0; j < 32; j++) {
                float v = __uint_as_float(r[j]) * msk + bias_s[cc * 32 + j];
                v = fmaxf(v, 0.0f);
                sumsq += v * v;
                vals[j] = v;
            }
#pragma unroll
            for (int j4 = 0; j4 < 8; j4++) {
                float4 o4 = make_float4(vals[j4*4], vals[j4*4+1],
                                        vals[j4*4+2], vals[j4*4+3]);
                *reinterpret_cast<float4*>(C + (size_t)m * ldc + n0 + cc * 32 + j4 * 4) = o4;
            }
        }
        part[(size_t)blockIdx.x * BATCH + m] = sumsq;
    }
    __syncthreads();
    if (tid == 0) { mbar_inval(sb + 8); mbar_inval(sb + 16); }
    __syncthreads();
    if (tid < 32) tmem_dealloc(tmem, 128);

#else  // ------- generic-target fallback (correct; never selected at runtime) --
    if (tid < TILE_M) {
        const int m = m0 + tid;
        const float msk = mask ? mask[m] : 1.0f;
        float sumsq = 0.0f;
        for (int nb = 0; nb < TILE_N; nb += 32) {
            float acc[32];
#pragma unroll
            for (int j = 0; j < 32; j++) acc[j] = 0.0f;
            for (int k = 0; k < lda; k++) {
                float a = A[(size_t)m * lda + k];
                for (int j = 0; j < 32; j++)
                    acc[j] += a * (BhT[(size_t)(n0 + nb + j) * KP + k] +
                                   BlT[(size_t)(n0 + nb + j) * KP + k]);
            }
            for (int j = 0; j < 32; j++) {
                float v = fmaxf(acc[j] * msk + bias[n0 + nb + j], 0.0f);
                sumsq += v * v;
                C[(size_t)m * ldc + n0 + nb + j] = v;
            }
        }
        part[(size_t)blockIdx.x * BATCH + m] = sumsq;
    }
#endif
}

// ---------------- combine partials -> norm + hist16 ---------------------------
__global__ void combine_kernel(const float* __restrict__ part, int nb,
                               float* __restrict__ norms, unsigned* __restrict__ hist) {
    int i = blockIdx.x * blockDim.x + threadIdx.x;
    if (i >= BATCH) return;
    float s = 0.0f;
    for (int b = 0; b < nb; b++) s += part[(size_t)b * BATCH + i];
    float n = sqrtf(s);
    norms[i] = n;
    atomicAdd(&hist[__float_as_uint(n) >> 16], 1u);
}

// ---------------- select threshold: hist16 prescan + 2x 8-bit refine ----------
__global__ void select_thr_kernel(const float* __restrict__ norms,
                                  const unsigned* __restrict__ hist,
                                  float* __restrict__ thr) {
    __shared__ unsigned psum[1024];
    __shared__ unsigned h8[256];
    __shared__ unsigned s_pref, s_rank;
    const int tid = threadIdx.x;

    unsigned s = 0;
#pragma unroll 8
    for (int j = 0; j < 64; j++) s += hist[tid * 64 + j];
    psum[tid] = s;
    __syncthreads();
    if (tid == 0) {
        unsigned cum = 0;
        int slice = 0;
        for (slice = 0; slice < 1024; slice++) {
            if (cum + psum[slice] > (unsigned)R_ASC) break;
            cum += psum[slice];
        }
        unsigned b = slice * 64;
        for (;; b++) {
            if (cum + hist[b] > (unsigned)R_ASC) break;
            cum += hist[b];
        }
        s_pref = b;
        s_rank = (unsigned)R_ASC - cum;
    }
    __syncthreads();

    if (tid < 256) h8[tid] = 0u;
    __syncthreads();
    unsigned pref16 = s_pref;
    for (int i = tid; i < BATCH; i += 1024) {
        unsigned u = __float_as_uint(norms[i]);
        if ((u >> 16) == pref16) atomicAdd(&h8[(u >> 8) & 0xffu], 1u);
    }
    __syncthreads();
    if (tid == 0) {
        unsigned cum = 0, b = 0, r = s_rank;
        for (b = 0; b < 256; b++) {
            if (cum + h8[b] > r) break;
            cum += h8[b];
        }
        s_pref = (pref16 << 8) | b;
        s_rank = r - cum;
    }
    __syncthreads();

    if (tid < 256) h8[tid] = 0u;
    __syncthreads();
    unsigned pref24 = s_pref;
    for (int i = tid; i < BATCH; i += 1024) {
        unsigned u = __float_as_uint(norms[i]);
        if ((u >> 8) == pref24) atomicAdd(&h8[u & 0xffu], 1u);
    }
    __syncthreads();
    if (tid == 0) {
        unsigned cum = 0, b = 0, r = s_rank;
        for (b = 0; b < 256; b++) {
            if (cum + h8[b] > r) break;
            cum += h8[b];
        }
        thr[0] = __uint_as_float((pref24 << 8) | b);
    }
}

__global__ void write_mask_kernel(const float* __restrict__ norms,
                                  const float* __restrict__ thr,
                                  float* __restrict__ ma, float* __restrict__ mb) {
    int i = blockIdx.x * blockDim.x + threadIdx.x;
    if (i >= BATCH) return;
    float mv = (norms[i] > thr[0]) ? 1.0f : 0.0f;
    ma[i] = mv;
    mb[i] = mv;
}

// ---------------- layer 3: [B,256] -> [B,10], relu, fused norm+hist ----------
__global__ __launch_bounds__(256)
void layer3_kernel(const float* __restrict__ H2, const float* __restrict__ mask2,
                   const float* __restrict__ W3, const float* __restrict__ b3,
                   float* __restrict__ H3, float* __restrict__ norms,
                   unsigned* __restrict__ hist) {
    __shared__ float Ws[D2 * D3];
    __shared__ float bs[D3];
    for (int i = threadIdx.x; i < D2 * D3; i += blockDim.x) Ws[i] = W3[i];
    if (threadIdx.x < D3) bs[threadIdx.x] = b3[threadIdx.x];
    __syncthreads();

    int row = (blockIdx.x * blockDim.x + threadIdx.x) >> 5;
    int lane = threadIdx.x & 31;
    if (row >= BATCH) return;
    float m = mask2[row];
    float p[D3];
#pragma unroll
    for (int n = 0; n < D3; n++) p[n] = 0.0f;
#pragma unroll
    for (int t = 0; t < D2 / 32; t++) {
        int k = lane + 32 * t;
        float a = H2[(size_t)row * D2 + k] * m;
        const float* wrow = &Ws[k * D3];
#pragma unroll
        for (int n = 0; n < D3; n++) p[n] += a * wrow[n];
    }
#pragma unroll
    for (int o = 16; o; o >>= 1)
#pragma unroll
        for (int n = 0; n < D3; n++) p[n] += __shfl_down_sync(0xffffffffu, p[n], o);

    if (lane == 0) {
        float ssum = 0.0f;
#pragma unroll
        for (int n = 0; n < D3; n++) {
            float v = fmaxf(p[n] + bs[n], 0.0f);
            H3[(size_t)row * D3 + n] = v;
            ssum += v * v;
        }
        float nr = sqrtf(ssum);
        norms[row] = nr;
        atomicAdd(&hist[__float_as_uint(nr) >> 16], 1u);
    }
}

// ---------------- layer 4 + fused norm+hist ----------------------------------
__global__ __launch_bounds__(256)
void layer4_kernel(const float* __restrict__ H3, const float* __restrict__ mask3,
                   const float* __restrict__ W4, const float* __restrict__ b4,
                   float* __restrict__ H4, float* __restrict__ norms,
                   unsigned* __restrict__ hist) {
    __shared__ float Ws[D3 * D3];
    __shared__ float bs[D3];
    if (threadIdx.x < D3 * D3) Ws[threadIdx.x] = W4[threadIdx.x];
    if (threadIdx.x < D3) bs[threadIdx.x] = b4[threadIdx.x];
    __syncthreads();

    int row = blockIdx.x * blockDim.x + threadIdx.x;
    if (row >= BATCH) return;
    float m = mask3[row];
    float a[D3];
#pragma unroll
    for (int k = 0; k < D3; k++) a[k] = H3[(size_t)row * D3 + k] * m;
    float ssum = 0.0f;
#pragma unroll
    for (int n = 0; n < D3; n++) {
        float v = bs[n];
#pragma unroll
        for (int k = 0; k < D3; k++) v += a[k] * Ws[k * D3 + n];
        H4[(size_t)row * D3 + n] = v;
        ssum += v * v;
    }
    float nr = sqrtf(ssum);
    norms[row] = nr;
    atomicAdd(&hist[__float_as_uint(nr) >> 16], 1u);
}

// ---------------- softmax over masked h4 -------------------------------------
__global__ __launch_bounds__(256)
void softmax_kernel(const float* __restrict__ H4, const float* __restrict__ norms,
                    const float* __restrict__ thr, float* __restrict__ out,
                    float* __restrict__ out_mask) {
    int row = blockIdx.x * blockDim.x + threadIdx.x;
    if (row >= BATCH) return;
    float m = (norms[row] > thr[0]) ? 1.0f : 0.0f;
    out_mask[row] = m;
    float v[D3];
    float mx = -1e30f;
#pragma unroll
    for (int n = 0; n < D3; n++) {
        v[n] = H4[(size_t)row * D3 + n] * m;
        mx = fmaxf(mx, v[n]);
    }
    float s = 0.0f;
#pragma unroll
    for (int n = 0; n < D3; n++) { v[n] = expf(v[n] - mx); s += v[n]; }
    float inv = 1.0f / s;
#pragma unroll
    for (int n = 0; n < D3; n++) out[(size_t)row * D3 + n] = v[n] * inv;
}

// ---------------- launch -----------------------------------------------------
extern "C" void kernel_launch(void* const* d_in, const int* in_sizes, int n_in,
                              void* d_out, int out_size) {
    const float* x  = (const float*)d_in[0];
    const float* W1 = (const float*)d_in[1];
    const float* b1 = (const float*)d_in[2];
    const float* W2 = (const float*)d_in[3];
    const float* b2 = (const float*)d_in[4];
    const float* W3 = (const float*)d_in[5];
    const float* b3 = (const float*)d_in[6];
    const float* W4 = (const float*)d_in[7];
    const float* b4 = (const float*)d_in[8];
    float* out = (float*)d_out;

    float *h1, *h2, *h3, *h4, *nrm, *m1, *m2, *m3, *part, *thr;
    float *w1h, *w1l, *w2h, *w2l;
    unsigned* hist;
    cudaGetSymbolAddress((void**)&h1, g_h1);
    cudaGetSymbolAddress((void**)&h2, g_h2);
    cudaGetSymbolAddress((void**)&h3, g_h3);
    cudaGetSymbolAddress((void**)&h4, g_h4);
    cudaGetSymbolAddress((void**)&nrm, g_norm);
    cudaGetSymbolAddress((void**)&m1, g_mask1);
    cudaGetSymbolAddress((void**)&m2, g_mask2);
    cudaGetSymbolAddress((void**)&m3, g_mask3);
    cudaGetSymbolAddress((void**)&part, g_part);
    cudaGetSymbolAddress((void**)&thr, g_thr);
    cudaGetSymbolAddress((void**)&w1h, g_w1hT);
    cudaGetSymbolAddress((void**)&w1l, g_w1lT);
    cudaGetSymbolAddress((void**)&w2h, g_w2hT);
    cudaGetSymbolAddress((void**)&w2l, g_w2lT);
    cudaGetSymbolAddress((void**)&hist, g_hist);

    cudaFuncSetAttribute(gemm_tc, cudaFuncAttributeMaxDynamicSharedMemorySize, GEMM_SMEM);

    float* out_m1 = out + (size_t)BATCH * D3;
    float* out_m2 = out_m1 + BATCH;
    float* out_m3 = out_m2 + BATCH;
    float* out_m4 = out_m3 + BATCH;

    unsigned* hist0 = hist;
    unsigned* hist1 = hist + 65536;
    unsigned* hist2 = hist + 2 * 65536;
    unsigned* hist3 = hist + 3 * 65536;

    zero_hists_kernel<<<(4 * 65536) / 256, 256>>>(hist);
    prep_split_T<<<(D1 * KP1 + 255) / 256, 256>>>(W1, w1h, w1l, D0, D1, KP1);
    prep_split_T<<<(D2 * KP2 + 255) / 256, 256>>>(W2, w2h, w2l, D1, D2, KP2);

    // Layer 1: [B,784] -> [B,512]
    {
        dim3 grid(D1 / TILE_N, BATCH / TILE_M);   // (4, 512)
        gemm_tc<<<grid, 256, GEMM_SMEM>>>(x, w1h, w1l, b1, nullptr,
                                          h1, part, D0, KP1, KP1 / CHUNK, D1);
    }
    combine_kernel<<<BATCH / 256, 256>>>(part, 4, nrm, hist0);
    select_thr_kernel<<<1, 1024>>>(nrm, hist0, thr);
    write_mask_kernel<<<BATCH / 256, 256>>>(nrm, thr, m1, out_m1);

    // Layer 2: [B,512] -> [B,256], mask in epilogue
    {
        dim3 grid(D2 / TILE_N, BATCH / TILE_M);   // (2, 512)
        gemm_tc<<<grid, 256, GEMM_SMEM>>>(h1, w2h, w2l, b2, m1,
                                          h2, part, D1, KP2, KP2 / CHUNK, D2);
    }
    combine_kernel<<<BATCH / 256, 256>>>(part, 2, nrm, hist1);
    select_thr_kernel<<<1, 1024>>>(nrm, hist1, thr);
    write_mask_kernel<<<BATCH / 256, 256>>>(nrm, thr, m2, out_m2);

    // Layer 3
    layer3_kernel<<<(BATCH * 32) / 256, 256>>>(h2, m2, W3, b3, h3, nrm, hist2);
    select_thr_kernel<<<1, 1024>>>(nrm, hist2, thr);
    write_mask_kernel<<<BATCH / 256, 256>>>(nrm, thr, m3, out_m3);

    // Layer 4
    layer4_kernel<<<BATCH / 256, 256>>>(h3, m3, W4, b4, h4, nrm, hist3);
    select_thr_kernel<<<1, 1024>>>(nrm, hist3, thr);

    // Softmax + mask4 write
    softmax_kernel<<<BATCH / 256, 256>>>(h4, nrm, thr, out, out_m4);
}

// round 10
// speedup vs baseline: 1.3613x; 1.3613x over previous
#include <cuda_runtime.h>
#include <math.h>
#include <stdint.h>

#define BATCH 65536
#define D0 784
#define D1 512
#define D2 256
#define D3 10
#define KP1 800            // 784 padded to 25*32 (B planes only)
#define KP2 512
#define K_DESC 32768
#define R_ASC (BATCH - 1 - K_DESC)   // 32767

#define TILE_M 128
#define TILE_N 256
#define CHUNK 32
#define NTHREADS 288       // 8 producer warps + 1 dispatcher warp
#define DISP_TID 256

// Does this compilation pass support tcgen05 (arch-specific sm_103a/sm_100a)?
#if defined(__CUDA_ARCH__) && (defined(__CUDA_ARCH_FEAT_SM103_ALL) || \
                               defined(__CUDA_ARCH_FEAT_SM100_ALL) || \
                               defined(__CUDA_ARCH_SPECIFIC__)     || \
                               defined(__CUDA_ARCH_FAMILY_SPECIFIC__))
#define USE_TC 1
#else
#define USE_TC 0
#endif

// tf32 SS MMA idesc: dtype=F32(1<<4), atype=TF32(2<<7), btype=TF32(2<<10),
// N field = (N/4)<<16, M field = (M/16)<<24
#define IDESC_TF32 ((1u<<4)|(2u<<7)|(2u<<10)|((256u/4)<<16)|((128u/16)<<24))

// SW128 smem descriptor base (layout=2, version=1, SBO=64, LBO=1)
#define DESC_BASE ((2ull<<61)|(1ull<<46)|(64ull<<32)|(1ull<<16))

// smem: [0..8) tmem ptr, [8..40) mbars (full0 full1 mma0 mma1), bias@1024
#define MB_FULL0 8
#define MB_FULL1 16
#define MB_MMA0  24
#define MB_MMA1  32
#define SM_BIAS  1024
#define SM_STAGE 2048
#define STAGE_BYTES 98304          // Ah 16K | Al 16K | Bh 32K | Bl 32K
#define OFF_AL 16384
#define OFF_BH 32768
#define OFF_BL 65536
#define GEMM_SMEM (SM_STAGE + 2 * STAGE_BYTES)

// ---------------- scratch -----------------------------------------------------
__device__ float g_h1[(size_t)BATCH * D1];
__device__ float g_h2[(size_t)BATCH * D2];
__device__ float g_h3[(size_t)BATCH * D3];
__device__ float g_h4[(size_t)BATCH * D3];
__device__ float g_norm[BATCH];
__device__ float g_mask1[BATCH];
__device__ float g_mask2[BATCH];
__device__ float g_mask3[BATCH];
__device__ float g_part[2 * BATCH];
__device__ float g_w1hT[(size_t)D1 * KP1];
__device__ float g_w1lT[(size_t)D1 * KP1];
__device__ float g_w2hT[(size_t)D2 * KP2];
__device__ float g_w2lT[(size_t)D2 * KP2];
__device__ unsigned g_hist[4][65536];
__device__ float g_thr[1];

// ---------------- helpers -----------------------------------------------------
__device__ __forceinline__ uint32_t smem_u32(const void* p) {
    uint32_t a;
    asm("{ .reg .u64 t; cvta.to.shared.u64 t, %1; cvt.u32.u64 %0, t; }" : "=r"(a) : "l"(p));
    return a;
}
__device__ __forceinline__ float trunc_tf32(float v) {
    return __uint_as_float(__float_as_uint(v) & 0xffffe000u);
}

#if USE_TC
__device__ __forceinline__ void cp16(uint32_t dst, const void* src) {
    asm volatile("cp.async.cg.shared.global [%0], [%1], 16;"
                 :: "r"(dst), "l"(src) : "memory");
}
__device__ __forceinline__ void cp_mbar_arrive_noinc(uint32_t mbar) {
    asm volatile("cp.async.mbarrier.arrive.noinc.shared.b64 [%0];"
                 :: "r"(mbar) : "memory");
}
__device__ __forceinline__ void sts128(uint32_t addr, float4 v) {
    asm volatile("st.shared.v4.f32 [%0], {%1,%2,%3,%4};"
                 :: "r"(addr), "f"(v.x), "f"(v.y), "f"(v.z), "f"(v.w) : "memory");
}
__device__ __forceinline__ void mbar_init(uint32_t addr, uint32_t cnt) {
    asm volatile("mbarrier.init.shared.b64 [%0], %1;" :: "r"(addr), "r"(cnt) : "memory");
}
__device__ __forceinline__ void mbar_inval(uint32_t addr) {
    asm volatile("mbarrier.inval.shared.b64 [%0];" :: "r"(addr) : "memory");
}
__device__ __forceinline__ void mbar_arrive(uint32_t addr) {
    asm volatile("mbarrier.arrive.shared.b64 _, [%0];" :: "r"(addr) : "memory");
}
__device__ __forceinline__ void mbar_wait(uint32_t addr, int parity) {
    asm volatile(
        "{\n\t.reg .pred P;\n"
        "WL_%=:\n\t"
        "mbarrier.try_wait.parity.acquire.cta.shared::cta.b64 P, [%0], %1, 0x989680;\n\t"
        "@P bra.uni WD_%=;\n\t"
        "bra.uni WL_%=;\n"
        "WD_%=:\n\t}"
        :: "r"(addr), "r"(parity) : "memory");
}
__device__ __forceinline__ void tmem_alloc(uint32_t smem_dst, uint32_t ncols) {
    asm volatile("tcgen05.alloc.cta_group::1.sync.aligned.shared::cta.b32 [%0], %1;"
                 :: "r"(smem_dst), "r"(ncols) : "memory");
}
__device__ __forceinline__ void tmem_dealloc(uint32_t tmem, uint32_t ncols) {
    asm volatile("tcgen05.relinquish_alloc_permit.cta_group::1.sync.aligned;");
    asm volatile("tcgen05.dealloc.cta_group::1.sync.aligned.b32 %0, %1;" :: "r"(tmem), "r"(ncols));
}
__device__ __forceinline__ void mma_tf32(uint32_t d, uint64_t ad, uint64_t bd, bool accum) {
    uint32_t en = accum ? 1u : 0u;
    asm volatile(
        "{\n\t.reg .pred p;\n\t"
        "setp.ne.u32 p, %4, 0;\n\t"
        "tcgen05.mma.cta_group::1.kind::tf32 [%0], %1, %2, %3, {%5,%5,%5,%5}, p;\n\t}"
        :: "r"(d), "l"(ad), "l"(bd), "r"(IDESC_TF32), "r"(en), "r"(0u) : "memory");
}
__device__ __forceinline__ void mma_commit(uint32_t mbar) {
    asm volatile("tcgen05.commit.cta_group::1.mbarrier::arrive::one.shared::cluster.b64 [%0];"
                 :: "r"(mbar) : "memory");
}
#define LDTM_X32(r, addr) \
    asm volatile( \
        "tcgen05.ld.sync.aligned.32x32b.x32.b32 " \
        "{%0, %1, %2, %3, %4, %5, %6, %7, " \
        " %8, %9, %10, %11, %12, %13, %14, %15, " \
        " %16, %17, %18, %19, %20, %21, %22, %23, " \
        " %24, %25, %26, %27, %28, %29, %30, %31}, [%32];" \
        : "=r"((r)[0]),  "=r"((r)[1]),  "=r"((r)[2]),  "=r"((r)[3]), \
          "=r"((r)[4]),  "=r"((r)[5]),  "=r"((r)[6]),  "=r"((r)[7]), \
          "=r"((r)[8]),  "=r"((r)[9]),  "=r"((r)[10]), "=r"((r)[11]), \
          "=r"((r)[12]), "=r"((r)[13]), "=r"((r)[14]), "=r"((r)[15]), \
          "=r"((r)[16]), "=r"((r)[17]), "=r"((r)[18]), "=r"((r)[19]), \
          "=r"((r)[20]), "=r"((r)[21]), "=r"((r)[22]), "=r"((r)[23]), \
          "=r"((r)[24]), "=r"((r)[25]), "=r"((r)[26]), "=r"((r)[27]), \
          "=r"((r)[28]), "=r"((r)[29]), "=r"((r)[30]), "=r"((r)[31]) \
        : "r"(addr))

__device__ __forceinline__ uint64_t mkdesc(uint32_t addr) {
    return DESC_BASE | ((uint64_t)(addr >> 4) & 0x3FFFull);
}
#endif  // USE_TC

// ---------------- weight transpose + tf32 split -------------------------------
__global__ void prep_split_T(const float* __restrict__ W, float* __restrict__ hiT,
                             float* __restrict__ loT, int K, int N, int KP) {
    int idx = blockIdx.x * blockDim.x + threadIdx.x;
    if (idx >= N * KP) return;
    int n = idx / KP, k = idx % KP;
    float v = (k < K) ? W[(size_t)k * N + n] : 0.0f;
    float h = trunc_tf32(v);
    hiT[idx] = h;
    loT[idx] = v - h;
}

__global__ void zero_hists_kernel(unsigned* h) {
    int i = blockIdx.x * blockDim.x + threadIdx.x;
    if (i < 4 * 65536) h[i] = 0u;
}

// ---------------- warp-specialized tcgen05 TF32 split-GEMM --------------------
// C = relu(mask[m]*(A @ B^T) + bias). 8 producer warps fill 2 SMEM stages
// (A split in regs + STS; B via cp.async with mbarrier completion); 1
// dispatcher warp issues 12 TF32 MMAs per chunk (hh, hl, lh). No __syncthreads
// in the mainloop. If hist != null: epilogue writes norms + hist16.
__global__ __launch_bounds__(NTHREADS)
void gemm_tc(const float* __restrict__ A, const float* __restrict__ BhT,
             const float* __restrict__ BlT, const float* __restrict__ bias,
             const float* __restrict__ mask, float* __restrict__ C,
             float* __restrict__ part, unsigned* __restrict__ hist,
             int lda, int KP, int nchunks, int ldc) {
    extern __shared__ char smem[];
    const int tid = threadIdx.x;
    const int m0 = blockIdx.y * TILE_M;
    const int n0 = blockIdx.x * TILE_N;

#if USE_TC
    const uint32_t sb = smem_u32(smem);
    float* bias_s = reinterpret_cast<float*>(smem + SM_BIAS);
    if (tid == 0) {
        mbar_init(sb + MB_FULL0, 512);
        mbar_init(sb + MB_FULL1, 512);
        mbar_init(sb + MB_MMA0, 1);
        mbar_init(sb + MB_MMA1, 1);
    }
    if (tid < 32) tmem_alloc(sb, 256);
    if (tid < TILE_N) bias_s[tid] = bias[n0 + tid];
    __syncthreads();
    uint32_t tmem;
    asm volatile("ld.shared.b32 %0, [%1];" : "=r"(tmem) : "r"(sb));

    if (tid < 256) {
        // ---------------- producer warps ----------------
        const int Klast = lda - 4;
        const int arow = tid >> 3;
        const int aq = tid & 7;
        const float* Abase = A + (size_t)m0 * lda;
        int mph0 = 0, mph1 = 0;

#pragma unroll 1
        for (int t = 0; t < nchunks; t++) {
            const int s = t & 1;
            const int k0 = t * CHUNK;
            const uint32_t full_b = sb + (s ? MB_FULL1 : MB_FULL0);
            const uint32_t stb = sb + SM_STAGE + s * STAGE_BYTES;

            // LDG A(t) first: latency overlaps the mma-wait below
            float4 va[4];
            {
                const int kA = k0 + aq * 4;
#pragma unroll
                for (int it = 0; it < 4; it++) {
                    const int row = arow + it * 32;
                    va[it] = (kA <= Klast)
                        ? *reinterpret_cast<const float4*>(Abase + (size_t)row * lda + kA)
                        : make_float4(0.f, 0.f, 0.f, 0.f);
                }
            }

            // stage reuse: MMA(t-2) must be done
            if (t >= 2) {
                if (s == 0) { mbar_wait(sb + MB_MMA0, mph0); mph0 ^= 1; }
                else        { mbar_wait(sb + MB_MMA1, mph1); mph1 ^= 1; }
            }

            // B planes via cp.async; completion -> full barrier
#pragma unroll
            for (int it = 0; it < 8; it++) {
                const int i = tid + it * 256;
                const int row = i >> 3, q = i & 7;
                const uint32_t off = row * 128 + q * 16;
                const uint32_t swo = off ^ ((off >> 3) & 0x70);
                const size_t goff = (size_t)(n0 + row) * KP + k0 + q * 4;
                cp16(stb + OFF_BH + swo, BhT + goff);
                cp16(stb + OFF_BL + swo, BlT + goff);
            }
            cp_mbar_arrive_noinc(full_b);

            // A split + STS
#pragma unroll
            for (int it = 0; it < 4; it++) {
                const int row = arow + it * 32;
                const uint32_t off = row * 128 + aq * 16;
                const uint32_t swo = off ^ ((off >> 3) & 0x70);
                float4 h, l;
                h.x = trunc_tf32(va[it].x); l.x = va[it].x - h.x;
                h.y = trunc_tf32(va[it].y); l.y = va[it].y - h.y;
                h.z = trunc_tf32(va[it].z); l.z = va[it].z - h.z;
                h.w = trunc_tf32(va[it].w); l.w = va[it].w - h.w;
                sts128(stb + swo, h);
                sts128(stb + OFF_AL + swo, l);
            }
            asm volatile("fence.proxy.async.shared::cta;" ::: "memory");
            mbar_arrive(full_b);
        }
    } else if (tid == DISP_TID) {
        // ---------------- dispatcher ----------------
        int fph0 = 0, fph1 = 0;
        int c0 = 0, c1 = 0;
#pragma unroll 1
        for (int t = 0; t < nchunks; t++) {
            const int s = t & 1;
            if (s == 0) { mbar_wait(sb + MB_FULL0, fph0); fph0 ^= 1; }
            else        { mbar_wait(sb + MB_FULL1, fph1); fph1 ^= 1; }
            const uint32_t stb = sb + SM_STAGE + s * STAGE_BYTES;
            const uint64_t dah = mkdesc(stb);
            const uint64_t dal = mkdesc(stb + OFF_AL);
            const uint64_t dbh = mkdesc(stb + OFF_BH);
            const uint64_t dbl = mkdesc(stb + OFF_BL);
#pragma unroll
            for (int ks = 0; ks < 4; ks++) {
                const uint64_t o = ks * 2;
                mma_tf32(tmem, dah + o, dbh + o, !(t == 0 && ks == 0));
                mma_tf32(tmem, dah + o, dbl + o, true);
                mma_tf32(tmem, dal + o, dbh + o, true);
            }
            if (s == 0) { mma_commit(sb + MB_MMA0); c0++; }
            else        { mma_commit(sb + MB_MMA1); c1++; }
        }
        // drain final MMA
        const int sl = (nchunks - 1) & 1;
        if (sl == 0) mbar_wait(sb + MB_MMA0, (c0 - 1) & 1);
        else         mbar_wait(sb + MB_MMA1, (c1 - 1) & 1);
    }
    __syncthreads();
    asm volatile("tcgen05.fence::after_thread_sync;" ::: "memory");

    // epilogue: warps 0-3 read TMEM D; bias+relu+mask, store, sumsq
    const int wid = tid >> 5, lane = tid & 31;
    if (wid < 4) {
        const int m = m0 + wid * 32 + lane;
        const float msk = mask ? mask[m] : 1.0f;
        float sumsq = 0.0f;
#pragma unroll 1
        for (int cc = 0; cc < 8; cc++) {
            uint32_t r[32];
            LDTM_X32(r, tmem + cc * 32);
            asm volatile("tcgen05.wait::ld.sync.aligned;" ::: "memory");
            float vals[32];
#pragma unroll
            for (int j = 0; j < 32; j++) {
                float v = __uint_as_float(r[j]) * msk + bias_s[cc * 32 + j];
                v = fmaxf(v, 0.0f);
                sumsq += v * v;
                vals[j] = v;
            }
#pragma unroll
            for (int j4 = 0; j4 < 8; j4++) {
                float4 o4 = make_float4(vals[j4*4], vals[j4*4+1],
                                        vals[j4*4+2], vals[j4*4+3]);
                *reinterpret_cast<float4*>(C + (size_t)m * ldc + n0 + cc * 32 + j4 * 4) = o4;
            }
        }
        if (hist) {
            float nr = sqrtf(sumsq);
            part[m] = nr;                 // here part == norms
            atomicAdd(&hist[__float_as_uint(nr) >> 16], 1u);
        } else {
            part[(size_t)blockIdx.x * BATCH + m] = sumsq;
        }
    }
    __syncthreads();
    if (tid == 0) {
        mbar_inval(sb + MB_FULL0); mbar_inval(sb + MB_FULL1);
        mbar_inval(sb + MB_MMA0);  mbar_inval(sb + MB_MMA1);
    }
    __syncthreads();
    if (tid < 32) tmem_dealloc(tmem, 256);

#else  // ------- generic-target fallback (correct; never selected at runtime) --
    if (tid < TILE_M) {
        const int m = m0 + tid;
        const float msk = mask ? mask[m] : 1.0f;
        float sumsq = 0.0f;
        for (int nb = 0; nb < TILE_N; nb += 32) {
            float acc[32];
#pragma unroll
            for (int j = 0; j < 32; j++) acc[j] = 0.0f;
            for (int k = 0; k < lda; k++) {
                float a = A[(size_t)m * lda + k];
                for (int j = 0; j < 32; j++)
                    acc[j] += a * (BhT[(size_t)(n0 + nb + j) * KP + k] +
                                   BlT[(size_t)(n0 + nb + j) * KP + k]);
            }
            for (int j = 0; j < 32; j++) {
                float v = fmaxf(acc[j] * msk + bias[n0 + nb + j], 0.0f);
                sumsq += v * v;
                C[(size_t)m * ldc + n0 + nb + j] = v;
            }
        }
        if (hist) {
            float nr = sqrtf(sumsq);
            part[m] = nr;
            atomicAdd(&hist[__float_as_uint(nr) >> 16], 1u);
        } else {
            part[(size_t)blockIdx.x * BATCH + m] = sumsq;
        }
    }
#endif
}

// ---------------- combine partials -> norm + hist16 ---------------------------
__global__ void combine_kernel(const float* __restrict__ part, int nb,
                               float* __restrict__ norms, unsigned* __restrict__ hist) {
    int i = blockIdx.x * blockDim.x + threadIdx.x;
    if (i >= BATCH) return;
    float s = 0.0f;
    for (int b = 0; b < nb; b++) s += part[(size_t)b * BATCH + i];
    float n = sqrtf(s);
    norms[i] = n;
    atomicAdd(&hist[__float_as_uint(n) >> 16], 1u);
}

// ---------------- select threshold: hist16 prescan + 2x 8-bit refine ----------
__global__ void select_thr_kernel(const float* __restrict__ norms,
                                  const unsigned* __restrict__ hist,
                                  float* __restrict__ thr) {
    __shared__ unsigned psum[1024];
    __shared__ unsigned h8[256];
    __shared__ unsigned s_pref, s_rank;
    const int tid = threadIdx.x;

    unsigned s = 0;
#pragma unroll 8
    for (int j = 0; j < 64; j++) s += hist[tid * 64 + j];
    psum[tid] = s;
    __syncthreads();
    if (tid == 0) {
        unsigned cum = 0;
        int slice = 0;
        for (slice = 0; slice < 1024; slice++) {
            if (cum + psum[slice] > (unsigned)R_ASC) break;
            cum += psum[slice];
        }
        unsigned b = slice * 64;
        for (;; b++) {
            if (cum + hist[b] > (unsigned)R_ASC) break;
            cum += hist[b];
        }
        s_pref = b;
        s_rank = (unsigned)R_ASC - cum;
    }
    __syncthreads();

    if (tid < 256) h8[tid] = 0u;
    __syncthreads();
    unsigned pref16 = s_pref;
    for (int i = tid; i < BATCH; i += 1024) {
        unsigned u = __float_as_uint(norms[i]);
        if ((u >> 16) == pref16) atomicAdd(&h8[(u >> 8) & 0xffu], 1u);
    }
    __syncthreads();
    if (tid == 0) {
        unsigned cum = 0, b = 0, r = s_rank;
        for (b = 0; b < 256; b++) {
            if (cum + h8[b] > r) break;
            cum += h8[b];
        }
        s_pref = (pref16 << 8) | b;
        s_rank = r - cum;
    }
    __syncthreads();

    if (tid < 256) h8[tid] = 0u;
    __syncthreads();
    unsigned pref24 = s_pref;
    for (int i = tid; i < BATCH; i += 1024) {
        unsigned u = __float_as_uint(norms[i]);
        if ((u >> 8) == pref24) atomicAdd(&h8[u & 0xffu], 1u);
    }
    __syncthreads();
    if (tid == 0) {
        unsigned cum = 0, b = 0, r = s_rank;
        for (b = 0; b < 256; b++) {
            if (cum + h8[b] > r) break;
            cum += h8[b];
        }
        thr[0] = __uint_as_float((pref24 << 8) | b);
    }
}

__global__ void write_mask_kernel(const float* __restrict__ norms,
                                  const float* __restrict__ thr,
                                  float* __restrict__ ma, float* __restrict__ mb) {
    int i = blockIdx.x * blockDim.x + threadIdx.x;
    if (i >= BATCH) return;
    float mv = (norms[i] > thr[0]) ? 1.0f : 0.0f;
    ma[i] = mv;
    mb[i] = mv;
}

// ---------------- layer 3: [B,256] -> [B,10], relu, fused norm+hist ----------
__global__ __launch_bounds__(256)
void layer3_kernel(const float* __restrict__ H2, const float* __restrict__ mask2,
                   const float* __restrict__ W3, const float* __restrict__ b3,
                   float* __restrict__ H3, float* __restrict__ norms,
                   unsigned* __restrict__ hist) {
    __shared__ float Ws[D2 * D3];
    __shared__ float bs[D3];
    for (int i = threadIdx.x; i < D2 * D3; i += blockDim.x) Ws[i] = W3[i];
    if (threadIdx.x < D3) bs[threadIdx.x] = b3[threadIdx.x];
    __syncthreads();

    int row = (blockIdx.x * blockDim.x + threadIdx.x) >> 5;
    int lane = threadIdx.x & 31;
    if (row >= BATCH) return;
    float m = mask2[row];
    float p[D3];
#pragma unroll
    for (int n = 0; n < D3; n++) p[n] = 0.0f;
#pragma unroll
    for (int t = 0; t < D2 / 32; t++) {
        int k = lane + 32 * t;
        float a = H2[(size_t)row * D2 + k] * m;
        const float* wrow = &Ws[k * D3];
#pragma unroll
        for (int n = 0; n < D3; n++) p[n] += a * wrow[n];
    }
#pragma unroll
    for (int o = 16; o; o >>= 1)
#pragma unroll
        for (int n = 0; n < D3; n++) p[n] += __shfl_down_sync(0xffffffffu, p[n], o);

    if (lane == 0) {
        float ssum = 0.0f;
#pragma unroll
        for (int n = 0; n < D3; n++) {
            float v = fmaxf(p[n] + bs[n], 0.0f);
            H3[(size_t)row * D3 + n] = v;
            ssum += v * v;
        }
        float nr = sqrtf(ssum);
        norms[row] = nr;
        atomicAdd(&hist[__float_as_uint(nr) >> 16], 1u);
    }
}

// ---------------- layer 4 + fused norm+hist ----------------------------------
__global__ __launch_bounds__(256)
void layer4_kernel(const float* __restrict__ H3, const float* __restrict__ mask3,
                   const float* __restrict__ W4, const float* __restrict__ b4,
                   float* __restrict__ H4, float* __restrict__ norms,
                   unsigned* __restrict__ hist) {
    __shared__ float Ws[D3 * D3];
    __shared__ float bs[D3];
    if (threadIdx.x < D3 * D3) Ws[threadIdx.x] = W4[threadIdx.x];
    if (threadIdx.x < D3) bs[threadIdx.x] = b4[threadIdx.x];
    __syncthreads();

    int row = blockIdx.x * blockDim.x + threadIdx.x;
    if (row >= BATCH) return;
    float m = mask3[row];
    float a[D3];
#pragma unroll
    for (int k = 0; k < D3; k++) a[k] = H3[(size_t)row * D3 + k] * m;
    float ssum = 0.0f;
#pragma unroll
    for (int n = 0; n < D3; n++) {
        float v = bs[n];
#pragma unroll
        for (int k = 0; k < D3; k++) v += a[k] * Ws[k * D3 + n];
        H4[(size_t)row * D3 + n] = v;
        ssum += v * v;
    }
    float nr = sqrtf(ssum);
    norms[row] = nr;
    atomicAdd(&hist[__float_as_uint(nr) >> 16], 1u);
}

// ---------------- softmax over masked h4 -------------------------------------
__global__ __launch_bounds__(256)
void softmax_kernel(const float* __restrict__ H4, const float* __restrict__ norms,
                    const float* __restrict__ thr, float* __restrict__ out,
                    float* __restrict__ out_mask) {
    int row = blockIdx.x * blockDim.x + threadIdx.x;
    if (row >= BATCH) return;
    float m = (norms[row] > thr[0]) ? 1.0f : 0.0f;
    out_mask[row] = m;
    float v[D3];
    float mx = -1e30f;
#pragma unroll
    for (int n = 0; n < D3; n++) {
        v[n] = H4[(size_t)row * D3 + n] * m;
        mx = fmaxf(mx, v[n]);
    }
    float s = 0.0f;
#pragma unroll
    for (int n = 0; n < D3; n++) { v[n] = expf(v[n] - mx); s += v[n]; }
    float inv = 1.0f / s;
#pragma unroll
    for (int n = 0; n < D3; n++) out[(size_t)row * D3 + n] = v[n] * inv;
}

// ---------------- launch -----------------------------------------------------
extern "C" void kernel_launch(void* const* d_in, const int* in_sizes, int n_in,
                              void* d_out, int out_size) {
    const float* x  = (const float*)d_in[0];
    const float* W1 = (const float*)d_in[1];
    const float* b1 = (const float*)d_in[2];
    const float* W2 = (const float*)d_in[3];
    const float* b2 = (const float*)d_in[4];
    const float* W3 = (const float*)d_in[5];
    const float* b3 = (const float*)d_in[6];
    const float* W4 = (const float*)d_in[7];
    const float* b4 = (const float*)d_in[8];
    float* out = (float*)d_out;

    float *h1, *h2, *h3, *h4, *nrm, *m1, *m2, *m3, *part, *thr;
    float *w1h, *w1l, *w2h, *w2l;
    unsigned* hist;
    cudaGetSymbolAddress((void**)&h1, g_h1);
    cudaGetSymbolAddress((void**)&h2, g_h2);
    cudaGetSymbolAddress((void**)&h3, g_h3);
    cudaGetSymbolAddress((void**)&h4, g_h4);
    cudaGetSymbolAddress((void**)&nrm, g_norm);
    cudaGetSymbolAddress((void**)&m1, g_mask1);
    cudaGetSymbolAddress((void**)&m2, g_mask2);
    cudaGetSymbolAddress((void**)&m3, g_mask3);
    cudaGetSymbolAddress((void**)&part, g_part);
    cudaGetSymbolAddress((void**)&thr, g_thr);
    cudaGetSymbolAddress((void**)&w1h, g_w1hT);
    cudaGetSymbolAddress((void**)&w1l, g_w1lT);
    cudaGetSymbolAddress((void**)&w2h, g_w2hT);
    cudaGetSymbolAddress((void**)&w2l, g_w2lT);
    cudaGetSymbolAddress((void**)&hist, g_hist);

    cudaFuncSetAttribute(gemm_tc, cudaFuncAttributeMaxDynamicSharedMemorySize, GEMM_SMEM);

    float* out_m1 = out + (size_t)BATCH * D3;
    float* out_m2 = out_m1 + BATCH;
    float* out_m3 = out_m2 + BATCH;
    float* out_m4 = out_m3 + BATCH;

    unsigned* hist0 = hist;
    unsigned* hist1 = hist + 65536;
    unsigned* hist2 = hist + 2 * 65536;
    unsigned* hist3 = hist + 3 * 65536;

    zero_hists_kernel<<<(4 * 65536) / 256, 256>>>(hist);
    prep_split_T<<<(D1 * KP1 + 255) / 256, 256>>>(W1, w1h, w1l, D0, D1, KP1);
    prep_split_T<<<(D2 * KP2 + 255) / 256, 256>>>(W2, w2h, w2l, D1, D2, KP2);

    // Layer 1: [B,784] -> [B,512]
    {
        dim3 grid(D1 / TILE_N, BATCH / TILE_M);   // (2, 512)
        gemm_tc<<<grid, NTHREADS, GEMM_SMEM>>>(x, w1h, w1l, b1, nullptr,
                                               h1, part, nullptr,
                                               D0, KP1, KP1 / CHUNK, D1);
    }
    combine_kernel<<<BATCH / 256, 256>>>(part, 2, nrm, hist0);
    select_thr_kernel<<<1, 1024>>>(nrm, hist0, thr);
    write_mask_kernel<<<BATCH / 256, 256>>>(nrm, thr, m1, out_m1);

    // Layer 2: [B,512] -> [B,256], mask in epilogue, fused norm+hist
    {
        dim3 grid(D2 / TILE_N, BATCH / TILE_M);   // (1, 512)
        gemm_tc<<<grid, NTHREADS, GEMM_SMEM>>>(h1, w2h, w2l, b2, m1,
                                               h2, nrm, hist1,
                                               D1, KP2, KP2 / CHUNK, D2);
    }
    select_thr_kernel<<<1, 1024>>>(nrm, hist1, thr);
    write_mask_kernel<<<BATCH / 256, 256>>>(nrm, thr, m2, out_m2);

    // Layer 3
    layer3_kernel<<<(BATCH * 32) / 256, 256>>>(h2, m2, W3, b3, h3, nrm, hist2);
    select_thr_kernel<<<1, 1024>>>(nrm, hist2, thr);
    write_mask_kernel<<<BATCH / 256, 256>>>(nrm, thr, m3, out_m3);

    // Layer 4
    layer4_kernel<<<BATCH / 256, 256>>>(h3, m3, W4, b4, h4, nrm, hist3);
    select_thr_kernel<<<1, 1024>>>(nrm, hist3, thr);

    // Softmax + mask4 write
    softmax_kernel<<<BATCH / 256, 256>>>(h4, nrm, thr, out, out_m4);
}

// round 12
// speedup vs baseline: 1.3807x; 1.0143x over previous
#include <cuda_runtime.h>
#include <math.h>
#include <stdint.h>

#define BATCH 65536
#define D0 784
#define D1 512
#define D2 256
#define D3 10
#define KP1 800            // 784 padded to 25*32 (B planes only)
#define KP2 512
#define K_DESC 32768
#define R_ASC (BATCH - 1 - K_DESC)   // 32767

#define TILE_M 128
#define TILE_N 256
#define CHUNK 32
#define NTHREADS 416       // warps 0-7 producers, 8-11 epilogue, 12 dispatcher
#define EPI_BASE 256
#define DISP_TID 384
#define GRID_P 148

// Does this compilation pass support tcgen05 (arch-specific sm_103a/sm_100a)?
#if defined(__CUDA_ARCH__) && (defined(__CUDA_ARCH_FEAT_SM103_ALL) || \
                               defined(__CUDA_ARCH_FEAT_SM100_ALL) || \
                               defined(__CUDA_ARCH_SPECIFIC__)     || \
                               defined(__CUDA_ARCH_FAMILY_SPECIFIC__))
#define USE_TC 1
#else
#define USE_TC 0
#endif

// tf32 SS MMA idesc: dtype=F32(1<<4), atype=TF32(2<<7), btype=TF32(2<<10),
// N field = (N/4)<<16, M field = (M/16)<<24
#define IDESC_TF32 ((1u<<4)|(2u<<7)|(2u<<10)|((256u/4)<<16)|((128u/16)<<24))

// SW128 smem descriptor base (layout=2, version=1, SBO=64, LBO=1)
#define DESC_BASE ((2ull<<61)|(1ull<<46)|(64ull<<32)|(1ull<<16))

// smem: [0..8) tmem ptr, mbars at 8..72, stages at 2048
#define MB_FULL0 8
#define MB_FULL1 16
#define MB_MMA0  24
#define MB_MMA1  32
#define MB_TD0   40
#define MB_TD1   48
#define MB_ED0   56
#define MB_ED1   64
#define SM_STAGE 2048
#define STAGE_BYTES 98304          // Ah 16K | Al 16K | Bh 32K | Bl 32K
#define OFF_AL 16384
#define OFF_BH 32768
#define OFF_BL 65536
#define GEMM_SMEM (SM_STAGE + 2 * STAGE_BYTES)

// ---------------- scratch -----------------------------------------------------
__device__ float g_h1[(size_t)BATCH * D1];
__device__ float g_h2[(size_t)BATCH * D2];
__device__ float g_h3[(size_t)BATCH * D3];
__device__ float g_h4[(size_t)BATCH * D3];
__device__ float g_norm[BATCH];
__device__ float g_mask1[BATCH];
__device__ float g_mask2[BATCH];
__device__ float g_mask3[BATCH];
__device__ float g_part[2 * BATCH];
__device__ float g_w1hT[(size_t)D1 * KP1];
__device__ float g_w1lT[(size_t)D1 * KP1];
__device__ float g_w2hT[(size_t)D2 * KP2];
__device__ float g_w2lT[(size_t)D2 * KP2];
__device__ unsigned g_hist[4][65536];
__device__ float g_thr[1];

// ---------------- helpers -----------------------------------------------------
__device__ __forceinline__ uint32_t smem_u32(const void* p) {
    uint32_t a;
    asm("{ .reg .u64 t; cvta.to.shared.u64 t, %1; cvt.u32.u64 %0, t; }" : "=r"(a) : "l"(p));
    return a;
}
__device__ __forceinline__ float trunc_tf32(float v) {
    return __uint_as_float(__float_as_uint(v) & 0xffffe000u);
}

#if USE_TC
__device__ __forceinline__ void cp16(uint32_t dst, const void* src) {
    asm volatile("cp.async.cg.shared.global [%0], [%1], 16;"
                 :: "r"(dst), "l"(src) : "memory");
}
__device__ __forceinline__ void cp_mbar_arrive_noinc(uint32_t mbar) {
    asm volatile("cp.async.mbarrier.arrive.noinc.shared.b64 [%0];"
                 :: "r"(mbar) : "memory");
}
__device__ __forceinline__ void sts128(uint32_t addr, float4 v) {
    asm volatile("st.shared.v4.f32 [%0], {%1,%2,%3,%4};"
                 :: "r"(addr), "f"(v.x), "f"(v.y), "f"(v.z), "f"(v.w) : "memory");
}
__device__ __forceinline__ void mbar_init(uint32_t addr, uint32_t cnt) {
    asm volatile("mbarrier.init.shared.b64 [%0], %1;" :: "r"(addr), "r"(cnt) : "memory");
}
__device__ __forceinline__ void mbar_inval(uint32_t addr) {
    asm volatile("mbarrier.inval.shared.b64 [%0];" :: "r"(addr) : "memory");
}
__device__ __forceinline__ void mbar_arrive(uint32_t addr) {
    asm volatile("mbarrier.arrive.shared.b64 _, [%0];" :: "r"(addr) : "memory");
}
__device__ __forceinline__ void mbar_wait(uint32_t addr, int parity) {
    asm volatile(
        "{\n\t.reg .pred P;\n"
        "WL_%=:\n\t"
        "mbarrier.try_wait.parity.acquire.cta.shared::cta.b64 P, [%0], %1, 0x989680;\n\t"
        "@P bra.uni WD_%=;\n\t"
        "bra.uni WL_%=;\n"
        "WD_%=:\n\t}"
        :: "r"(addr), "r"(parity) : "memory");
}
__device__ __forceinline__ void tmem_alloc(uint32_t smem_dst, uint32_t ncols) {
    asm volatile("tcgen05.alloc.cta_group::1.sync.aligned.shared::cta.b32 [%0], %1;"
                 :: "r"(smem_dst), "r"(ncols) : "memory");
}
__device__ __forceinline__ void tmem_dealloc(uint32_t tmem, uint32_t ncols) {
    asm volatile("tcgen05.relinquish_alloc_permit.cta_group::1.sync.aligned;");
    asm volatile("tcgen05.dealloc.cta_group::1.sync.aligned.b32 %0, %1;" :: "r"(tmem), "r"(ncols));
}
__device__ __forceinline__ void mma_tf32(uint32_t d, uint64_t ad, uint64_t bd, bool accum) {
    uint32_t en = accum ? 1u : 0u;
    asm volatile(
        "{\n\t.reg .pred p;\n\t"
        "setp.ne.u32 p, %4, 0;\n\t"
        "tcgen05.mma.cta_group::1.kind::tf32 [%0], %1, %2, %3, {%5,%5,%5,%5}, p;\n\t}"
        :: "r"(d), "l"(ad), "l"(bd), "r"(IDESC_TF32), "r"(en), "r"(0u) : "memory");
}
__device__ __forceinline__ void mma_commit(uint32_t mbar) {
    asm volatile("tcgen05.commit.cta_group::1.mbarrier::arrive::one.shared::cluster.b64 [%0];"
                 :: "r"(mbar) : "memory");
}
#define LDTM_X32(r, addr) \
    asm volatile( \
        "tcgen05.ld.sync.aligned.32x32b.x32.b32 " \
        "{%0, %1, %2, %3, %4, %5, %6, %7, " \
        " %8, %9, %10, %11, %12, %13, %14, %15, " \
        " %16, %17, %18, %19, %20, %21, %22, %23, " \
        " %24, %25, %26, %27, %28, %29, %30, %31}, [%32];" \
        : "=r"((r)[0]),  "=r"((r)[1]),  "=r"((r)[2]),  "=r"((r)[3]), \
          "=r"((r)[4]),  "=r"((r)[5]),  "=r"((r)[6]),  "=r"((r)[7]), \
          "=r"((r)[8]),  "=r"((r)[9]),  "=r"((r)[10]), "=r"((r)[11]), \
          "=r"((r)[12]), "=r"((r)[13]), "=r"((r)[14]), "=r"((r)[15]), \
          "=r"((r)[16]), "=r"((r)[17]), "=r"((r)[18]), "=r"((r)[19]), \
          "=r"((r)[20]), "=r"((r)[21]), "=r"((r)[22]), "=r"((r)[23]), \
          "=r"((r)[24]), "=r"((r)[25]), "=r"((r)[26]), "=r"((r)[27]), \
          "=r"((r)[28]), "=r"((r)[29]), "=r"((r)[30]), "=r"((r)[31]) \
        : "r"(addr))

__device__ __forceinline__ uint64_t mkdesc(uint32_t addr) {
    return DESC_BASE | ((uint64_t)(addr >> 4) & 0x3FFFull);
}
#endif  // USE_TC

// ---------------- weight transpose + tf32 split -------------------------------
__global__ void prep_split_T(const float* __restrict__ W, float* __restrict__ hiT,
                             float* __restrict__ loT, int K, int N, int KP) {
    int idx = blockIdx.x * blockDim.x + threadIdx.x;
    if (idx >= N * KP) return;
    int n = idx / KP, k = idx % KP;
    float v = (k < K) ? W[(size_t)k * N + n] : 0.0f;
    float h = trunc_tf32(v);
    hiT[idx] = h;
    loT[idx] = v - h;
}

__global__ void zero_hists_kernel(unsigned* h) {
    int i = blockIdx.x * blockDim.x + threadIdx.x;
    if (i < 4 * 65536) h[i] = 0u;
}

// ---------------- persistent warp-specialized tcgen05 TF32 split-GEMM ---------
// C = relu(mask[m]*(A @ B^T) + bias). Persistent CTAs loop tiles; warps 0-7
// fill 2 SMEM stages (phases continuous across tiles); warp 12 dispatches 12
// TF32 MMAs/chunk into TMEM D buffer (tile&1), commits tile-done; warps 8-11
// (subpartition-aligned: wid%4 == ewid) drain the other D buffer concurrently.
__global__ __launch_bounds__(NTHREADS)
void gemm_tc(const float* __restrict__ A, const float* __restrict__ BhT,
             const float* __restrict__ BlT, const float* __restrict__ bias,
             const float* __restrict__ mask, float* __restrict__ C,
             float* __restrict__ part, unsigned* __restrict__ hist,
             int lda, int KP, int nchunks, int ldc, int ntiles, int nblk) {
    extern __shared__ char smem[];
    const int tid = threadIdx.x;

#if USE_TC
    const uint32_t sb = smem_u32(smem);
    if (tid == 0) {
        mbar_init(sb + MB_FULL0, 512);
        mbar_init(sb + MB_FULL1, 512);
        mbar_init(sb + MB_MMA0, 1);
        mbar_init(sb + MB_MMA1, 1);
        mbar_init(sb + MB_TD0, 1);
        mbar_init(sb + MB_TD1, 1);
        mbar_init(sb + MB_ED0, 128);
        mbar_init(sb + MB_ED1, 128);
    }
    if (tid < 32) tmem_alloc(sb, 512);
    __syncthreads();
    uint32_t tmem;
    asm volatile("ld.shared.b32 %0, [%1];" : "=r"(tmem) : "r"(sb));

    if (tid < 256) {
        // ---------------- producer warps (0-7) ----------------
        const int Klast = lda - 4;
        const int arow = tid >> 3;
        const int aq = tid & 7;
        int mph0 = 0, mph1 = 0;
        int g = 0;

#pragma unroll 1
        for (int T = blockIdx.x; T < ntiles; T += GRID_P) {
            const int m0 = (T / nblk) * TILE_M;
            const int n0 = (T % nblk) * TILE_N;
            const float* Abase = A + (size_t)m0 * lda;
#pragma unroll 1
            for (int t = 0; t < nchunks; t++, g++) {
                const int s = g & 1;
                const int k0 = t * CHUNK;
                const uint32_t full_b = sb + (s ? MB_FULL1 : MB_FULL0);
                const uint32_t stb = sb + SM_STAGE + s * STAGE_BYTES;

                // LDG A(t): latency overlaps the mma-wait below
                float4 va[4];
                {
                    const int kA = k0 + aq * 4;
#pragma unroll
                    for (int it = 0; it < 4; it++) {
                        const int row = arow + it * 32;
                        va[it] = (kA <= Klast)
                            ? *reinterpret_cast<const float4*>(Abase + (size_t)row * lda + kA)
                            : make_float4(0.f, 0.f, 0.f, 0.f);
                    }
                }

                // stage reuse: MMA(g-2) must be done
                if (g >= 2) {
                    if (s == 0) { mbar_wait(sb + MB_MMA0, mph0); mph0 ^= 1; }
                    else        { mbar_wait(sb + MB_MMA1, mph1); mph1 ^= 1; }
                }

                // B planes via cp.async; completion -> full barrier
#pragma unroll
                for (int it = 0; it < 8; it++) {
                    const int i = tid + it * 256;
                    const int row = i >> 3, q = i & 7;
                    const uint32_t off = row * 128 + q * 16;
                    const uint32_t swo = off ^ ((off >> 3) & 0x70);
                    const size_t goff = (size_t)(n0 + row) * KP + k0 + q * 4;
                    cp16(stb + OFF_BH + swo, BhT + goff);
                    cp16(stb + OFF_BL + swo, BlT + goff);
                }
                cp_mbar_arrive_noinc(full_b);

                // A split + STS
#pragma unroll
                for (int it = 0; it < 4; it++) {
                    const int row = arow + it * 32;
                    const uint32_t off = row * 128 + aq * 16;
                    const uint32_t swo = off ^ ((off >> 3) & 0x70);
                    float4 h, l;
                    h.x = trunc_tf32(va[it].x); l.x = va[it].x - h.x;
                    h.y = trunc_tf32(va[it].y); l.y = va[it].y - h.y;
                    h.z = trunc_tf32(va[it].z); l.z = va[it].z - h.z;
                    h.w = trunc_tf32(va[it].w); l.w = va[it].w - h.w;
                    sts128(stb + swo, h);
                    sts128(stb + OFF_AL + swo, l);
                }
                asm volatile("fence.proxy.async.shared::cta;" ::: "memory");
                mbar_arrive(full_b);
            }
        }
    } else if (tid < EPI_BASE + 128) {
        // ---------------- epilogue warps (8-11; wid%4 == ewid) ----------------
        const int etid = tid - EPI_BASE;     // 0..127
        const int ewid = etid >> 5;          // == warp_id % 4 (subpartition)
        const int lane = etid & 31;
        int tph0 = 0, tph1 = 0;
        int ti = 0;
#pragma unroll 1
        for (int T = blockIdx.x; T < ntiles; T += GRID_P, ti++) {
            const int d = ti & 1;
            if (d == 0) { mbar_wait(sb + MB_TD0, tph0); tph0 ^= 1; }
            else        { mbar_wait(sb + MB_TD1, tph1); tph1 ^= 1; }
            asm volatile("tcgen05.fence::after_thread_sync;" ::: "memory");

            const int m0 = (T / nblk) * TILE_M;
            const int n0 = (T % nblk) * TILE_N;
            const int m = m0 + ewid * 32 + lane;
            const float msk = mask ? mask[m] : 1.0f;
            float sumsq = 0.0f;
#pragma unroll 1
            for (int cc = 0; cc < 8; cc++) {
                uint32_t r[32];
                LDTM_X32(r, tmem + d * 256 + cc * 32);
                asm volatile("tcgen05.wait::ld.sync.aligned;" ::: "memory");
                float vals[32];
#pragma unroll
                for (int j = 0; j < 32; j++) {
                    float v = __uint_as_float(r[j]) * msk + __ldg(bias + n0 + cc * 32 + j);
                    v = fmaxf(v, 0.0f);
                    sumsq += v * v;
                    vals[j] = v;
                }
#pragma unroll
                for (int j4 = 0; j4 < 8; j4++) {
                    float4 o4 = make_float4(vals[j4*4], vals[j4*4+1],
                                            vals[j4*4+2], vals[j4*4+3]);
                    *reinterpret_cast<float4*>(C + (size_t)m * ldc + n0 + cc * 32 + j4 * 4) = o4;
                }
            }
            asm volatile("tcgen05.fence::before_thread_sync;" ::: "memory");
            mbar_arrive(sb + (d ? MB_ED1 : MB_ED0));

            if (hist) {
                float nr = sqrtf(sumsq);
                part[m] = nr;            // here part == norms
                atomicAdd(&hist[__float_as_uint(nr) >> 16], 1u);
            } else {
                part[(size_t)(T % nblk) * BATCH + m] = sumsq;
            }
        }
    } else if (tid == DISP_TID) {
        // ---------------- dispatcher (warp 12, lane 0) ----------------
        int fph0 = 0, fph1 = 0;
        int eph0 = 0, eph1 = 0;
        int g = 0, ti = 0;
#pragma unroll 1
        for (int T = blockIdx.x; T < ntiles; T += GRID_P, ti++) {
            const int d = ti & 1;
            if (ti >= 2) {
                if (d == 0) { mbar_wait(sb + MB_ED0, eph0); eph0 ^= 1; }
                else        { mbar_wait(sb + MB_ED1, eph1); eph1 ^= 1; }
                asm volatile("tcgen05.fence::after_thread_sync;" ::: "memory");
            }
            const uint32_t dtm = tmem + d * 256;
#pragma unroll 1
            for (int t = 0; t < nchunks; t++, g++) {
                const int s = g & 1;
                if (s == 0) { mbar_wait(sb + MB_FULL0, fph0); fph0 ^= 1; }
                else        { mbar_wait(sb + MB_FULL1, fph1); fph1 ^= 1; }
                const uint32_t stb = sb + SM_STAGE + s * STAGE_BYTES;
                const uint64_t dah = mkdesc(stb);
                const uint64_t dal = mkdesc(stb + OFF_AL);
                const uint64_t dbh = mkdesc(stb + OFF_BH);
                const uint64_t dbl = mkdesc(stb + OFF_BL);
#pragma unroll
                for (int ks = 0; ks < 4; ks++) {
                    const uint64_t o = ks * 2;
                    mma_tf32(dtm, dah + o, dbh + o, !(t == 0 && ks == 0));
                    mma_tf32(dtm, dah + o, dbl + o, true);
                    mma_tf32(dtm, dal + o, dbh + o, true);
                }
                mma_commit(sb + (s ? MB_MMA1 : MB_MMA0));
            }
            // tile done (tracks all prior MMAs) -> epilogue may drain buffer d
            mma_commit(sb + (d ? MB_TD1 : MB_TD0));
        }
    }
    __syncthreads();
    if (tid == 0) {
        mbar_inval(sb + MB_FULL0); mbar_inval(sb + MB_FULL1);
        mbar_inval(sb + MB_MMA0);  mbar_inval(sb + MB_MMA1);
        mbar_inval(sb + MB_TD0);   mbar_inval(sb + MB_TD1);
        mbar_inval(sb + MB_ED0);   mbar_inval(sb + MB_ED1);
    }
    __syncthreads();
    if (tid < 32) tmem_dealloc(tmem, 512);

#else  // ------- generic-target fallback (correct; never selected at runtime) --
    for (int T = blockIdx.x; T < ntiles; T += GRID_P) {
        const int m0 = (T / nblk) * TILE_M;
        const int n0 = (T % nblk) * TILE_N;
        if (tid < TILE_M) {
            const int m = m0 + tid;
            const float msk = mask ? mask[m] : 1.0f;
            float sumsq = 0.0f;
            for (int nb = 0; nb < TILE_N; nb += 32) {
                float acc[32];
#pragma unroll
                for (int j = 0; j < 32; j++) acc[j] = 0.0f;
                for (int k = 0; k < lda; k++) {
                    float a = A[(size_t)m * lda + k];
                    for (int j = 0; j < 32; j++)
                        acc[j] += a * (BhT[(size_t)(n0 + nb + j) * KP + k] +
                                       BlT[(size_t)(n0 + nb + j) * KP + k]);
                }
                for (int j = 0; j < 32; j++) {
                    float v = fmaxf(acc[j] * msk + bias[n0 + nb + j], 0.0f);
                    sumsq += v * v;
                    C[(size_t)m * ldc + n0 + nb + j] = v;
                }
            }
            if (hist) {
                float nr = sqrtf(sumsq);
                part[m] = nr;
                atomicAdd(&hist[__float_as_uint(nr) >> 16], 1u);
            } else {
                part[(size_t)(T % nblk) * BATCH + m] = sumsq;
            }
        }
    }
#endif
}

// ---------------- combine partials -> norm + hist16 ---------------------------
__global__ void combine_kernel(const float* __restrict__ part, int nb,
                               float* __restrict__ norms, unsigned* __restrict__ hist) {
    int i = blockIdx.x * blockDim.x + threadIdx.x;
    if (i >= BATCH) return;
    float s = 0.0f;
    for (int b = 0; b < nb; b++) s += part[(size_t)b * BATCH + i];
    float n = sqrtf(s);
    norms[i] = n;
    atomicAdd(&hist[__float_as_uint(n) >> 16], 1u);
}

// ---------------- select threshold: hist16 prescan + 2x 8-bit refine ----------
__global__ void select_thr_kernel(const float* __restrict__ norms,
                                  const unsigned* __restrict__ hist,
                                  float* __restrict__ thr) {
    __shared__ unsigned psum[1024];
    __shared__ unsigned h8[256];
    __shared__ unsigned s_pref, s_rank;
    const int tid = threadIdx.x;

    unsigned s = 0;
#pragma unroll 8
    for (int j = 0; j < 64; j++) s += hist[tid * 64 + j];
    psum[tid] = s;
    __syncthreads();
    if (tid == 0) {
        unsigned cum = 0;
        int slice = 0;
        for (slice = 0; slice < 1024; slice++) {
            if (cum + psum[slice] > (unsigned)R_ASC) break;
            cum += psum[slice];
        }
        unsigned b = slice * 64;
        for (;; b++) {
            if (cum + hist[b] > (unsigned)R_ASC) break;
            cum += hist[b];
        }
        s_pref = b;
        s_rank = (unsigned)R_ASC - cum;
    }
    __syncthreads();

    if (tid < 256) h8[tid] = 0u;
    __syncthreads();
    unsigned pref16 = s_pref;
    for (int i = tid; i < BATCH; i += 1024) {
        unsigned u = __float_as_uint(norms[i]);
        if ((u >> 16) == pref16) atomicAdd(&h8[(u >> 8) & 0xffu], 1u);
    }
    __syncthreads();
    if (tid == 0) {
        unsigned cum = 0, b = 0, r = s_rank;
        for (b = 0; b < 256; b++) {
            if (cum + h8[b] > r) break;
            cum += h8[b];
        }
        s_pref = (pref16 << 8) | b;
        s_rank = r - cum;
    }
    __syncthreads();

    if (tid < 256) h8[tid] = 0u;
    __syncthreads();
    unsigned pref24 = s_pref;
    for (int i = tid; i < BATCH; i += 1024) {
        unsigned u = __float_as_uint(norms[i]);
        if ((u >> 8) == pref24) atomicAdd(&h8[u & 0xffu], 1u);
    }
    __syncthreads();
    if (tid == 0) {
        unsigned cum = 0, b = 0, r = s_rank;
        for (b = 0; b < 256; b++) {
            if (cum + h8[b] > r) break;
            cum += h8[b];
        }
        thr[0] = __uint_as_float((pref24 << 8) | b);
    }
}

__global__ void write_mask_kernel(const float* __restrict__ norms,
                                  const float* __restrict__ thr,
                                  float* __restrict__ ma, float* __restrict__ mb) {
    int i = blockIdx.x * blockDim.x + threadIdx.x;
    if (i >= BATCH) return;
    float mv = (norms[i] > thr[0]) ? 1.0f : 0.0f;
    ma[i] = mv;
    mb[i] = mv;
}

// ---------------- layer 3: [B,256] -> [B,10], relu, fused norm+hist ----------
__global__ __launch_bounds__(256)
void layer3_kernel(const float* __restrict__ H2, const float* __restrict__ mask2,
                   const float* __restrict__ W3, const float* __restrict__ b3,
                   float* __restrict__ H3, float* __restrict__ norms,
                   unsigned* __restrict__ hist) {
    __shared__ float Ws[D2 * D3];
    __shared__ float bs[D3];
    for (int i = threadIdx.x; i < D2 * D3; i += blockDim.x) Ws[i] = W3[i];
    if (threadIdx.x < D3) bs[threadIdx.x] = b3[threadIdx.x];
    __syncthreads();

    int row = (blockIdx.x * blockDim.x + threadIdx.x) >> 5;
    int lane = threadIdx.x & 31;
    if (row >= BATCH) return;
    float m = mask2[row];
    float p[D3];
#pragma unroll
    for (int n = 0; n < D3; n++) p[n] = 0.0f;
#pragma unroll
    for (int t = 0; t < D2 / 32; t++) {
        int k = lane + 32 * t;
        float a = H2[(size_t)row * D2 + k] * m;
        const float* wrow = &Ws[k * D3];
#pragma unroll
        for (int n = 0; n < D3; n++) p[n] += a * wrow[n];
    }
#pragma unroll
    for (int o = 16; o; o >>= 1)
#pragma unroll
        for (int n = 0; n < D3; n++) p[n] += __shfl_down_sync(0xffffffffu, p[n], o);

    if (lane == 0) {
        float ssum = 0.0f;
#pragma unroll
        for (int n = 0; n < D3; n++) {
            float v = fmaxf(p[n] + bs[n], 0.0f);
            H3[(size_t)row * D3 + n] = v;
            ssum += v * v;
        }
        float nr = sqrtf(ssum);
        norms[row] = nr;
        atomicAdd(&hist[__float_as_uint(nr) >> 16], 1u);
    }
}

// ---------------- layer 4 + fused norm+hist ----------------------------------
__global__ __launch_bounds__(256)
void layer4_kernel(const float* __restrict__ H3, const float* __restrict__ mask3,
                   const float* __restrict__ W4, const float* __restrict__ b4,
                   float* __restrict__ H4, float* __restrict__ norms,
                   unsigned* __restrict__ hist) {
    __shared__ float Ws[D3 * D3];
    __shared__ float bs[D3];
    if (threadIdx.x < D3 * D3) Ws[threadIdx.x] = W4[threadIdx.x];
    if (threadIdx.x < D3) bs[threadIdx.x] = b4[threadIdx.x];
    __syncthreads();

    int row = blockIdx.x * blockDim.x + threadIdx.x;
    if (row >= BATCH) return;
    float m = mask3[row];
    float a[D3];
#pragma unroll
    for (int k = 0; k < D3; k++) a[k] = H3[(size_t)row * D3 + k] * m;
    float ssum = 0.0f;
#pragma unroll
    for (int n = 0; n < D3; n++) {
        float v = bs[n];
#pragma unroll
        for (int k = 0; k < D3; k++) v += a[k] * Ws[k * D3 + n];
        H4[(size_t)row * D3 + n] = v;
        ssum += v * v;
    }
    float nr = sqrtf(ssum);
    norms[row] = nr;
    atomicAdd(&hist[__float_as_uint(nr) >> 16], 1u);
}

// ---------------- softmax over masked h4 -------------------------------------
__global__ __launch_bounds__(256)
void softmax_kernel(const float* __restrict__ H4, const float* __restrict__ norms,
                    const float* __restrict__ thr, float* __restrict__ out,
                    float* __restrict__ out_mask) {
    int row = blockIdx.x * blockDim.x + threadIdx.x;
    if (row >= BATCH) return;
    float m = (norms[row] > thr[0]) ? 1.0f : 0.0f;
    out_mask[row] = m;
    float v[D3];
    float mx = -1e30f;
#pragma unroll
    for (int n = 0; n < D3; n++) {
        v[n] = H4[(size_t)row * D3 + n] * m;
        mx = fmaxf(mx, v[n]);
    }
    float s = 0.0f;
#pragma unroll
    for (int n = 0; n < D3; n++) { v[n] = expf(v[n] - mx); s += v[n]; }
    float inv = 1.0f / s;
#pragma unroll
    for (int n = 0; n < D3; n++) out[(size_t)row * D3 + n] = v[n] * inv;
}

// ---------------- launch -----------------------------------------------------
extern "C" void kernel_launch(void* const* d_in, const int* in_sizes, int n_in,
                              void* d_out, int out_size) {
    const float* x  = (const float*)d_in[0];
    const float* W1 = (const float*)d_in[1];
    const float* b1 = (const float*)d_in[2];
    const float* W2 = (const float*)d_in[3];
    const float* b2 = (const float*)d_in[4];
    const float* W3 = (const float*)d_in[5];
    const float* b3 = (const float*)d_in[6];
    const float* W4 = (const float*)d_in[7];
    const float* b4 = (const float*)d_in[8];
    float* out = (float*)d_out;

    float *h1, *h2, *h3, *h4, *nrm, *m1, *m2, *m3, *part, *thr;
    float *w1h, *w1l, *w2h, *w2l;
    unsigned* hist;
    cudaGetSymbolAddress((void**)&h1, g_h1);
    cudaGetSymbolAddress((void**)&h2, g_h2);
    cudaGetSymbolAddress((void**)&h3, g_h3);
    cudaGetSymbolAddress((void**)&h4, g_h4);
    cudaGetSymbolAddress((void**)&nrm, g_norm);
    cudaGetSymbolAddress((void**)&m1, g_mask1);
    cudaGetSymbolAddress((void**)&m2, g_mask2);
    cudaGetSymbolAddress((void**)&m3, g_mask3);
    cudaGetSymbolAddress((void**)&part, g_part);
    cudaGetSymbolAddress((void**)&thr, g_thr);
    cudaGetSymbolAddress((void**)&w1h, g_w1hT);
    cudaGetSymbolAddress((void**)&w1l, g_w1lT);
    cudaGetSymbolAddress((void**)&w2h, g_w2hT);
    cudaGetSymbolAddress((void**)&w2l, g_w2lT);
    cudaGetSymbolAddress((void**)&hist, g_hist);

    cudaFuncSetAttribute(gemm_tc, cudaFuncAttributeMaxDynamicSharedMemorySize, GEMM_SMEM);

    float* out_m1 = out + (size_t)BATCH * D3;
    float* out_m2 = out_m1 + BATCH;
    float* out_m3 = out_m2 + BATCH;
    float* out_m4 = out_m3 + BATCH;

    unsigned* hist0 = hist;
    unsigned* hist1 = hist + 65536;
    unsigned* hist2 = hist + 2 * 65536;
    unsigned* hist3 = hist + 3 * 65536;

    zero_hists_kernel<<<(4 * 65536) / 256, 256>>>(hist);
    prep_split_T<<<(D1 * KP1 + 255) / 256, 256>>>(W1, w1h, w1l, D0, D1, KP1);
    prep_split_T<<<(D2 * KP2 + 255) / 256, 256>>>(W2, w2h, w2l, D1, D2, KP2);

    // Layer 1: [B,784] -> [B,512]; ntiles = 2 n-blocks x 512 m-blocks
    {
        const int ntiles = (D1 / TILE_N) * (BATCH / TILE_M);   // 1024
        gemm_tc<<<GRID_P, NTHREADS, GEMM_SMEM>>>(x, w1h, w1l, b1, nullptr,
                                                 h1, part, nullptr,
                                                 D0, KP1, KP1 / CHUNK, D1,
                                                 ntiles, D1 / TILE_N);
    }
    combine_kernel<<<BATCH / 256, 256>>>(part, 2, nrm, hist0);
    select_thr_kernel<<<1, 1024>>>(nrm, hist0, thr);
    write_mask_kernel<<<BATCH / 256, 256>>>(nrm, thr, m1, out_m1);

    // Layer 2: [B,512] -> [B,256], mask in epilogue, fused norm+hist
    {
        const int ntiles = (D2 / TILE_N) * (BATCH / TILE_M);   // 512
        gemm_tc<<<GRID_P, NTHREADS, GEMM_SMEM>>>(h1, w2h, w2l, b2, m1,
                                                 h2, nrm, hist1,
                                                 D1, KP2, KP2 / CHUNK, D2,
                                                 ntiles, D2 / TILE_N);
    }
    select_thr_kernel<<<1, 1024>>>(nrm, hist1, thr);
    write_mask_kernel<<<BATCH / 256, 256>>>(nrm, thr, m2, out_m2);

    // Layer 3
    layer3_kernel<<<(BATCH * 32) / 256, 256>>>(h2, m2, W3, b3, h3, nrm, hist2);
    select_thr_kernel<<<1, 1024>>>(nrm, hist2, thr);
    write_mask_kernel<<<BATCH / 256, 256>>>(nrm, thr, m3, out_m3);

    // Layer 4
    layer4_kernel<<<BATCH / 256, 256>>>(h3, m3, W4, b4, h4, nrm, hist3);
    select_thr_kernel<<<1, 1024>>>(nrm, hist3, thr);

    // Softmax + mask4 write
    softmax_kernel<<<BATCH / 256, 256>>>(h4, nrm, thr, out, out_m4);
}

// round 13
// speedup vs baseline: 1.5924x; 1.1533x over previous
#include <cuda_runtime.h>
#include <math.h>
#include <stdint.h>

#define BATCH 65536
#define D0 784
#define D1 512
#define D2 256
#define D3 10
#define KP1 800            // 784 padded to 25*32 (B planes only)
#define KP2 512
#define K_DESC 32768
#define R_ASC (BATCH - 1 - K_DESC)   // 32767

#define TILE_M 128
#define TILE_N 256
#define CHUNK 32
#define NTHREADS 416       // warps 0-7 producers, 8-11 epilogue, 12 dispatcher
#define EPI_BASE 256
#define DISP_TID 384
#define GRID_P 148

// Does this compilation pass support tcgen05 (arch-specific sm_103a/sm_100a)?
#if defined(__CUDA_ARCH__) && (defined(__CUDA_ARCH_FEAT_SM103_ALL) || \
                               defined(__CUDA_ARCH_FEAT_SM100_ALL) || \
                               defined(__CUDA_ARCH_SPECIFIC__)     || \
                               defined(__CUDA_ARCH_FAMILY_SPECIFIC__))
#define USE_TC 1
#else
#define USE_TC 0
#endif

// tf32 SS MMA idesc
#define IDESC_TF32 ((1u<<4)|(2u<<7)|(2u<<10)|((256u/4)<<16)|((128u/16)<<24))
// SW128 smem descriptor base (layout=2, version=1, SBO=64, LBO=1)
#define DESC_BASE ((2ull<<61)|(1ull<<46)|(64ull<<32)|(1ull<<16))

// smem: [0..8) tmem ptr, mbars at 8..72, stages at 2048
#define MB_FULL0 8
#define MB_FULL1 16
#define MB_MMA0  24
#define MB_MMA1  32
#define MB_TD0   40
#define MB_TD1   48
#define MB_ED0   56
#define MB_ED1   64
#define SM_STAGE 2048
#define STAGE_BYTES 98304          // Ah 16K | Al 16K | Bh 32K | Bl 32K
#define OFF_AL 16384
#define OFF_BH 32768
#define OFF_BL 65536
#define GEMM_SMEM (SM_STAGE + 2 * STAGE_BYTES)

// ---------------- scratch -----------------------------------------------------
__device__ float g_h1[(size_t)BATCH * D1];
__device__ float g_h2[(size_t)BATCH * D2];
__device__ float g_h3[(size_t)BATCH * D3];
__device__ float g_h4[(size_t)BATCH * D3];
__device__ float g_norm[BATCH];
__device__ float g_part[2 * BATCH];
__device__ float g_w1hT[(size_t)D1 * KP1];
__device__ float g_w1lT[(size_t)D1 * KP1];
__device__ float g_w2hT[(size_t)D2 * KP2];
__device__ float g_w2lT[(size_t)D2 * KP2];
__device__ unsigned g_hist[4][65536];
__device__ unsigned g_psum[4][1024];
__device__ float g_thr[4];

// ---------------- helpers -----------------------------------------------------
__device__ __forceinline__ uint32_t smem_u32(const void* p) {
    uint32_t a;
    asm("{ .reg .u64 t; cvta.to.shared.u64 t, %1; cvt.u32.u64 %0, t; }" : "=r"(a) : "l"(p));
    return a;
}
__device__ __forceinline__ float trunc_tf32(float v) {
    return __uint_as_float(__float_as_uint(v) & 0xffffe000u);
}
__device__ __forceinline__ void hist_add(unsigned* hist, unsigned* psum, float nr) {
    unsigned b = __float_as_uint(nr) >> 16;
    atomicAdd(&hist[b], 1u);
    atomicAdd(&psum[b >> 6], 1u);
}

#if USE_TC
__device__ __forceinline__ void cp16(uint32_t dst, const void* src) {
    asm volatile("cp.async.cg.shared.global [%0], [%1], 16;"
                 :: "r"(dst), "l"(src) : "memory");
}
__device__ __forceinline__ void cp_mbar_arrive_noinc(uint32_t mbar) {
    asm volatile("cp.async.mbarrier.arrive.noinc.shared.b64 [%0];"
                 :: "r"(mbar) : "memory");
}
__device__ __forceinline__ void sts128(uint32_t addr, float4 v) {
    asm volatile("st.shared.v4.f32 [%0], {%1,%2,%3,%4};"
                 :: "r"(addr), "f"(v.x), "f"(v.y), "f"(v.z), "f"(v.w) : "memory");
}
__device__ __forceinline__ void mbar_init(uint32_t addr, uint32_t cnt) {
    asm volatile("mbarrier.init.shared.b64 [%0], %1;" :: "r"(addr), "r"(cnt) : "memory");
}
__device__ __forceinline__ void mbar_inval(uint32_t addr) {
    asm volatile("mbarrier.inval.shared.b64 [%0];" :: "r"(addr) : "memory");
}
__device__ __forceinline__ void mbar_arrive(uint32_t addr) {
    asm volatile("mbarrier.arrive.shared.b64 _, [%0];" :: "r"(addr) : "memory");
}
__device__ __forceinline__ void mbar_wait(uint32_t addr, int parity) {
    asm volatile(
        "{\n\t.reg .pred P;\n"
        "WL_%=:\n\t"
        "mbarrier.try_wait.parity.acquire.cta.shared::cta.b64 P, [%0], %1, 0x989680;\n\t"
        "@P bra.uni WD_%=;\n\t"
        "bra.uni WL_%=;\n"
        "WD_%=:\n\t}"
        :: "r"(addr), "r"(parity) : "memory");
}
__device__ __forceinline__ void tmem_alloc(uint32_t smem_dst, uint32_t ncols) {
    asm volatile("tcgen05.alloc.cta_group::1.sync.aligned.shared::cta.b32 [%0], %1;"
                 :: "r"(smem_dst), "r"(ncols) : "memory");
}
__device__ __forceinline__ void tmem_dealloc(uint32_t tmem, uint32_t ncols) {
    asm volatile("tcgen05.relinquish_alloc_permit.cta_group::1.sync.aligned;");
    asm volatile("tcgen05.dealloc.cta_group::1.sync.aligned.b32 %0, %1;" :: "r"(tmem), "r"(ncols));
}
__device__ __forceinline__ void mma_tf32(uint32_t d, uint64_t ad, uint64_t bd, bool accum) {
    uint32_t en = accum ? 1u : 0u;
    asm volatile(
        "{\n\t.reg .pred p;\n\t"
        "setp.ne.u32 p, %4, 0;\n\t"
        "tcgen05.mma.cta_group::1.kind::tf32 [%0], %1, %2, %3, {%5,%5,%5,%5}, p;\n\t}"
        :: "r"(d), "l"(ad), "l"(bd), "r"(IDESC_TF32), "r"(en), "r"(0u) : "memory");
}
__device__ __forceinline__ void mma_commit(uint32_t mbar) {
    asm volatile("tcgen05.commit.cta_group::1.mbarrier::arrive::one.shared::cluster.b64 [%0];"
                 :: "r"(mbar) : "memory");
}
#define LDTM_X32(r, addr) \
    asm volatile( \
        "tcgen05.ld.sync.aligned.32x32b.x32.b32 " \
        "{%0, %1, %2, %3, %4, %5, %6, %7, " \
        " %8, %9, %10, %11, %12, %13, %14, %15, " \
        " %16, %17, %18, %19, %20, %21, %22, %23, " \
        " %24, %25, %26, %27, %28, %29, %30, %31}, [%32];" \
        : "=r"((r)[0]),  "=r"((r)[1]),  "=r"((r)[2]),  "=r"((r)[3]), \
          "=r"((r)[4]),  "=r"((r)[5]),  "=r"((r)[6]),  "=r"((r)[7]), \
          "=r"((r)[8]),  "=r"((r)[9]),  "=r"((r)[10]), "=r"((r)[11]), \
          "=r"((r)[12]), "=r"((r)[13]), "=r"((r)[14]), "=r"((r)[15]), \
          "=r"((r)[16]), "=r"((r)[17]), "=r"((r)[18]), "=r"((r)[19]), \
          "=r"((r)[20]), "=r"((r)[21]), "=r"((r)[22]), "=r"((r)[23]), \
          "=r"((r)[24]), "=r"((r)[25]), "=r"((r)[26]), "=r"((r)[27]), \
          "=r"((r)[28]), "=r"((r)[29]), "=r"((r)[30]), "=r"((r)[31]) \
        : "r"(addr))

__device__ __forceinline__ uint64_t mkdesc(uint32_t addr) {
    return DESC_BASE | ((uint64_t)(addr >> 4) & 0x3FFFull);
}
#endif  // USE_TC

// ---------------- merged prep: zero hists/psums + split both W ----------------
__global__ void prep_kernel(const float* __restrict__ W1, float* __restrict__ w1h,
                            float* __restrict__ w1l, const float* __restrict__ W2,
                            float* __restrict__ w2h, float* __restrict__ w2l,
                            unsigned* __restrict__ hist, unsigned* __restrict__ psum) {
    int idx = blockIdx.x * blockDim.x + threadIdx.x;
    // zero hists (4*65536) and psums (4*1024)
    if (idx < 4 * 65536) hist[idx] = 0u;
    if (idx < 4 * 1024) psum[idx] = 0u;
    // W1 split: D1*KP1 = 409600
    if (idx < D1 * KP1) {
        int n = idx / KP1, k = idx % KP1;
        float v = (k < D0) ? W1[(size_t)k * D1 + n] : 0.0f;
        float h = trunc_tf32(v);
        w1h[idx] = h;
        w1l[idx] = v - h;
    }
    // W2 split: D2*KP2 = 131072
    if (idx < D2 * KP2) {
        int n = idx / KP2, k = idx % KP2;
        float v = (k < D1) ? W2[(size_t)k * D2 + n] : 0.0f;
        float h = trunc_tf32(v);
        w2h[idx] = h;
        w2l[idx] = v - h;
    }
}

// ---------------- persistent warp-specialized tcgen05 TF32 split-GEMM ---------
// C = relu(msk*(A @ B^T) + bias). Warps 0-7 produce, 8-11 epilogue (wid%4
// aligned), 12 dispatches. If hist != null (layer-2 mode): epilogue computes
// msk = norms_in[m] > thr_in[0], writes mask_out[m], writes new norms + hist.
// Else: plain relu, per-(n-block,row) sumsq partial into part.
__global__ __launch_bounds__(NTHREADS)
void gemm_tc(const float* __restrict__ A, const float* __restrict__ BhT,
             const float* __restrict__ BlT, const float* __restrict__ bias,
             const float* __restrict__ norms_in, const float* __restrict__ thr_in,
             float* __restrict__ mask_out, float* __restrict__ C,
             float* __restrict__ part, unsigned* __restrict__ hist,
             unsigned* __restrict__ psum,
             int lda, int KP, int nchunks, int ldc, int ntiles, int nblk) {
    extern __shared__ char smem[];
    const int tid = threadIdx.x;

#if USE_TC
    const uint32_t sb = smem_u32(smem);
    if (tid == 0) {
        mbar_init(sb + MB_FULL0, 512);
        mbar_init(sb + MB_FULL1, 512);
        mbar_init(sb + MB_MMA0, 1);
        mbar_init(sb + MB_MMA1, 1);
        mbar_init(sb + MB_TD0, 1);
        mbar_init(sb + MB_TD1, 1);
        mbar_init(sb + MB_ED0, 128);
        mbar_init(sb + MB_ED1, 128);
    }
    if (tid < 32) tmem_alloc(sb, 512);
    __syncthreads();
    uint32_t tmem;
    asm volatile("ld.shared.b32 %0, [%1];" : "=r"(tmem) : "r"(sb));

    if (tid < 256) {
        // ---------------- producer warps (0-7) ----------------
        const int Klast = lda - 4;
        const int arow = tid >> 3;
        const int aq = tid & 7;
        int mph0 = 0, mph1 = 0;
        int g = 0;

#pragma unroll 1
        for (int T = blockIdx.x; T < ntiles; T += GRID_P) {
            const int m0 = (T / nblk) * TILE_M;
            const int n0 = (T % nblk) * TILE_N;
            const float* Abase = A + (size_t)m0 * lda;
#pragma unroll 1
            for (int t = 0; t < nchunks; t++, g++) {
                const int s = g & 1;
                const int k0 = t * CHUNK;
                const uint32_t full_b = sb + (s ? MB_FULL1 : MB_FULL0);
                const uint32_t stb = sb + SM_STAGE + s * STAGE_BYTES;

                // LDG A(t): latency overlaps the mma-wait below
                float4 va[4];
                {
                    const int kA = k0 + aq * 4;
#pragma unroll
                    for (int it = 0; it < 4; it++) {
                        const int row = arow + it * 32;
                        va[it] = (kA <= Klast)
                            ? *reinterpret_cast<const float4*>(Abase + (size_t)row * lda + kA)
                            : make_float4(0.f, 0.f, 0.f, 0.f);
                    }
                }

                // stage reuse: MMA(g-2) must be done
                if (g >= 2) {
                    if (s == 0) { mbar_wait(sb + MB_MMA0, mph0); mph0 ^= 1; }
                    else        { mbar_wait(sb + MB_MMA1, mph1); mph1 ^= 1; }
                }

                // B planes via cp.async; completion -> full barrier
#pragma unroll
                for (int it = 0; it < 8; it++) {
                    const int i = tid + it * 256;
                    const int row = i >> 3, q = i & 7;
                    const uint32_t off = row * 128 + q * 16;
                    const uint32_t swo = off ^ ((off >> 3) & 0x70);
                    const size_t goff = (size_t)(n0 + row) * KP + k0 + q * 4;
                    cp16(stb + OFF_BH + swo, BhT + goff);
                    cp16(stb + OFF_BL + swo, BlT + goff);
                }
                cp_mbar_arrive_noinc(full_b);

                // A split + STS
#pragma unroll
                for (int it = 0; it < 4; it++) {
                    const int row = arow + it * 32;
                    const uint32_t off = row * 128 + aq * 16;
                    const uint32_t swo = off ^ ((off >> 3) & 0x70);
                    float4 h, l;
                    h.x = trunc_tf32(va[it].x); l.x = va[it].x - h.x;
                    h.y = trunc_tf32(va[it].y); l.y = va[it].y - h.y;
                    h.z = trunc_tf32(va[it].z); l.z = va[it].z - h.z;
                    h.w = trunc_tf32(va[it].w); l.w = va[it].w - h.w;
                    sts128(stb + swo, h);
                    sts128(stb + OFF_AL + swo, l);
                }
                asm volatile("fence.proxy.async.shared::cta;" ::: "memory");
                mbar_arrive(full_b);
            }
        }
    } else if (tid < EPI_BASE + 128) {
        // ---------------- epilogue warps (8-11; wid%4 == ewid) ----------------
        const int etid = tid - EPI_BASE;     // 0..127
        const int ewid = etid >> 5;          // == warp_id % 4 (subpartition)
        const int lane = etid & 31;
        int tph0 = 0, tph1 = 0;
        int ti = 0;
        const float thrv = thr_in ? thr_in[0] : 0.0f;
#pragma unroll 1
        for (int T = blockIdx.x; T < ntiles; T += GRID_P, ti++) {
            const int d = ti & 1;
            if (d == 0) { mbar_wait(sb + MB_TD0, tph0); tph0 ^= 1; }
            else        { mbar_wait(sb + MB_TD1, tph1); tph1 ^= 1; }
            asm volatile("tcgen05.fence::after_thread_sync;" ::: "memory");

            const int m0 = (T / nblk) * TILE_M;
            const int n0 = (T % nblk) * TILE_N;
            const int m = m0 + ewid * 32 + lane;
            float msk = 1.0f;
            if (norms_in) {
                msk = (norms_in[m] > thrv) ? 1.0f : 0.0f;
                mask_out[m] = msk;
            }
            float sumsq = 0.0f;
#pragma unroll 1
            for (int cc = 0; cc < 8; cc++) {
                uint32_t r[32];
                LDTM_X32(r, tmem + d * 256 + cc * 32);
                asm volatile("tcgen05.wait::ld.sync.aligned;" ::: "memory");
                float vals[32];
#pragma unroll
                for (int j = 0; j < 32; j++) {
                    float v = __uint_as_float(r[j]) * msk + __ldg(bias + n0 + cc * 32 + j);
                    v = fmaxf(v, 0.0f);
                    sumsq += v * v;
                    vals[j] = v;
                }
#pragma unroll
                for (int j4 = 0; j4 < 8; j4++) {
                    float4 o4 = make_float4(vals[j4*4], vals[j4*4+1],
                                            vals[j4*4+2], vals[j4*4+3]);
                    *reinterpret_cast<float4*>(C + (size_t)m * ldc + n0 + cc * 32 + j4 * 4) = o4;
                }
            }
            asm volatile("tcgen05.fence::before_thread_sync;" ::: "memory");
            mbar_arrive(sb + (d ? MB_ED1 : MB_ED0));

            if (hist) {
                float nr = sqrtf(sumsq);
                part[m] = nr;            // here part == norms (layer-2 output)
                hist_add(hist, psum, nr);
            } else {
                part[(size_t)(T % nblk) * BATCH + m] = sumsq;
            }
        }
    } else if (tid == DISP_TID) {
        // ---------------- dispatcher (warp 12, lane 0) ----------------
        int fph0 = 0, fph1 = 0;
        int eph0 = 0, eph1 = 0;
        int g = 0, ti = 0;
#pragma unroll 1
        for (int T = blockIdx.x; T < ntiles; T += GRID_P, ti++) {
            const int d = ti & 1;
            if (ti >= 2) {
                if (d == 0) { mbar_wait(sb + MB_ED0, eph0); eph0 ^= 1; }
                else        { mbar_wait(sb + MB_ED1, eph1); eph1 ^= 1; }
                asm volatile("tcgen05.fence::after_thread_sync;" ::: "memory");
            }
            const uint32_t dtm = tmem + d * 256;
#pragma unroll 1
            for (int t = 0; t < nchunks; t++, g++) {
                const int s = g & 1;
                if (s == 0) { mbar_wait(sb + MB_FULL0, fph0); fph0 ^= 1; }
                else        { mbar_wait(sb + MB_FULL1, fph1); fph1 ^= 1; }
                const uint32_t stb = sb + SM_STAGE + s * STAGE_BYTES;
                const uint64_t dah = mkdesc(stb);
                const uint64_t dal = mkdesc(stb + OFF_AL);
                const uint64_t dbh = mkdesc(stb + OFF_BH);
                const uint64_t dbl = mkdesc(stb + OFF_BL);
#pragma unroll
                for (int ks = 0; ks < 4; ks++) {
                    const uint64_t o = ks * 2;
                    mma_tf32(dtm, dah + o, dbh + o, !(t == 0 && ks == 0));
                    mma_tf32(dtm, dah + o, dbl + o, true);
                    mma_tf32(dtm, dal + o, dbh + o, true);
                }
                mma_commit(sb + (s ? MB_MMA1 : MB_MMA0));
            }
            // tile done (tracks all prior MMAs) -> epilogue may drain buffer d
            mma_commit(sb + (d ? MB_TD1 : MB_TD0));
        }
    }
    __syncthreads();
    if (tid == 0) {
        mbar_inval(sb + MB_FULL0); mbar_inval(sb + MB_FULL1);
        mbar_inval(sb + MB_MMA0);  mbar_inval(sb + MB_MMA1);
        mbar_inval(sb + MB_TD0);   mbar_inval(sb + MB_TD1);
        mbar_inval(sb + MB_ED0);   mbar_inval(sb + MB_ED1);
    }
    __syncthreads();
    if (tid < 32) tmem_dealloc(tmem, 512);

#else  // ------- generic-target fallback (correct; never selected at runtime) --
    const float thrv = thr_in ? thr_in[0] : 0.0f;
    for (int T = blockIdx.x; T < ntiles; T += GRID_P) {
        const int m0 = (T / nblk) * TILE_M;
        const int n0 = (T % nblk) * TILE_N;
        if (tid < TILE_M) {
            const int m = m0 + tid;
            float msk = 1.0f;
            if (norms_in) {
                msk = (norms_in[m] > thrv) ? 1.0f : 0.0f;
                mask_out[m] = msk;
            }
            float sumsq = 0.0f;
            for (int nb = 0; nb < TILE_N; nb += 32) {
                float acc[32];
#pragma unroll
                for (int j = 0; j < 32; j++) acc[j] = 0.0f;
                for (int k = 0; k < lda; k++) {
                    float a = A[(size_t)m * lda + k];
                    for (int j = 0; j < 32; j++)
                        acc[j] += a * (BhT[(size_t)(n0 + nb + j) * KP + k] +
                                       BlT[(size_t)(n0 + nb + j) * KP + k]);
                }
                for (int j = 0; j < 32; j++) {
                    float v = fmaxf(acc[j] * msk + bias[n0 + nb + j], 0.0f);
                    sumsq += v * v;
                    C[(size_t)m * ldc + n0 + nb + j] = v;
                }
            }
            if (hist) {
                float nr = sqrtf(sumsq);
                part[m] = nr;
                hist_add(hist, psum, nr);
            } else {
                part[(size_t)(T % nblk) * BATCH + m] = sumsq;
            }
        }
    }
#endif
}

// ---------------- combine partials -> norm + hist16 + psum --------------------
__global__ void combine_kernel(const float* __restrict__ part, int nb,
                               float* __restrict__ norms, unsigned* __restrict__ hist,
                               unsigned* __restrict__ psum) {
    int i = blockIdx.x * blockDim.x + threadIdx.x;
    if (i >= BATCH) return;
    float s = 0.0f;
    for (int b = 0; b < nb; b++) s += part[(size_t)b * BATCH + i];
    float n = sqrtf(s);
    norms[i] = n;
    hist_add(hist, psum, n);
}

// ---------------- select threshold: psum-staged prescan + 2x 8-bit refine -----
__global__ void select_thr_kernel(const float* __restrict__ norms,
                                  const unsigned* __restrict__ hist,
                                  const unsigned* __restrict__ psum,
                                  float* __restrict__ thr) {
    __shared__ unsigned ps[1024];
    __shared__ unsigned h8[256];
    __shared__ unsigned s_pref, s_rank, s_slice;
    const int tid = threadIdx.x;

    ps[tid] = psum[tid];
    __syncthreads();
    if (tid == 0) {
        unsigned cum = 0;
        int slice = 0;
        for (slice = 0; slice < 1024; slice++) {
            if (cum + ps[slice] > (unsigned)R_ASC) break;
            cum += ps[slice];
        }
        s_slice = slice;
        s_rank = (unsigned)R_ASC - cum;
    }
    __syncthreads();
    // stage the 64 hist bins of the selected slice
    if (tid < 64) h8[tid] = hist[s_slice * 64 + tid];
    __syncthreads();
    if (tid == 0) {
        unsigned cum = 0, r = s_rank, b = 0;
        for (b = 0; b < 64; b++) {
            if (cum + h8[b] > r) break;
            cum += h8[b];
        }
        s_pref = s_slice * 64 + b;       // 16-bit prefix
        s_rank = r - cum;
    }
    __syncthreads();

    // refine bits [15:8]
    if (tid < 256) h8[tid] = 0u;
    __syncthreads();
    unsigned pref16 = s_pref;
    for (int i = tid; i < BATCH; i += 1024) {
        unsigned u = __float_as_uint(norms[i]);
        if ((u >> 16) == pref16) atomicAdd(&h8[(u >> 8) & 0xffu], 1u);
    }
    __syncthreads();
    if (tid == 0) {
        unsigned cum = 0, b = 0, r = s_rank;
        for (b = 0; b < 256; b++) {
            if (cum + h8[b] > r) break;
            cum += h8[b];
        }
        s_pref = (pref16 << 8) | b;
        s_rank = r - cum;
    }
    __syncthreads();

    // refine bits [7:0]
    if (tid < 256) h8[tid] = 0u;
    __syncthreads();
    unsigned pref24 = s_pref;
    for (int i = tid; i < BATCH; i += 1024) {
        unsigned u = __float_as_uint(norms[i]);
        if ((u >> 8) == pref24) atomicAdd(&h8[u & 0xffu], 1u);
    }
    __syncthreads();
    if (tid == 0) {
        unsigned cum = 0, b = 0, r = s_rank;
        for (b = 0; b < 256; b++) {
            if (cum + h8[b] > r) break;
            cum += h8[b];
        }
        thr[0] = __uint_as_float((pref24 << 8) | b);
    }
}

// ---------------- layer 3: mask2 inline, relu, fused norm+hist+mask2-out ------
__global__ __launch_bounds__(256)
void layer3_kernel(const float* __restrict__ H2, const float* __restrict__ norms_in,
                   const float* __restrict__ thr_in, float* __restrict__ mask_out,
                   const float* __restrict__ W3, const float* __restrict__ b3,
                   float* __restrict__ H3, float* __restrict__ norms,
                   unsigned* __restrict__ hist, unsigned* __restrict__ psum) {
    __shared__ float Ws[D2 * D3];
    __shared__ float bs[D3];
    for (int i = threadIdx.x; i < D2 * D3; i += blockDim.x) Ws[i] = W3[i];
    if (threadIdx.x < D3) bs[threadIdx.x] = b3[threadIdx.x];
    __syncthreads();

    int row = (blockIdx.x * blockDim.x + threadIdx.x) >> 5;
    int lane = threadIdx.x & 31;
    if (row >= BATCH) return;
    float m = (norms_in[row] > thr_in[0]) ? 1.0f : 0.0f;
    if (lane == 0) mask_out[row] = m;
    float p[D3];
#pragma unroll
    for (int n = 0; n < D3; n++) p[n] = 0.0f;
#pragma unroll
    for (int t = 0; t < D2 / 32; t++) {
        int k = lane + 32 * t;
        float a = H2[(size_t)row * D2 + k] * m;
        const float* wrow = &Ws[k * D3];
#pragma unroll
        for (int n = 0; n < D3; n++) p[n] += a * wrow[n];
    }
#pragma unroll
    for (int o = 16; o; o >>= 1)
#pragma unroll
        for (int n = 0; n < D3; n++) p[n] += __shfl_down_sync(0xffffffffu, p[n], o);

    if (lane == 0) {
        float ssum = 0.0f;
#pragma unroll
        for (int n = 0; n < D3; n++) {
            float v = fmaxf(p[n] + bs[n], 0.0f);
            H3[(size_t)row * D3 + n] = v;
            ssum += v * v;
        }
        float nr = sqrtf(ssum);
        norms[row] = nr;
        hist_add(hist, psum, nr);
    }
}

// ---------------- layer 4: mask3 inline + fused norm+hist+mask3-out -----------
__global__ __launch_bounds__(256)
void layer4_kernel(const float* __restrict__ H3, const float* __restrict__ norms_in,
                   const float* __restrict__ thr_in, float* __restrict__ mask_out,
                   const float* __restrict__ W4, const float* __restrict__ b4,
                   float* __restrict__ H4, float* __restrict__ norms,
                   unsigned* __restrict__ hist, unsigned* __restrict__ psum) {
    __shared__ float Ws[D3 * D3];
    __shared__ float bs[D3];
    if (threadIdx.x < D3 * D3) Ws[threadIdx.x] = W4[threadIdx.x];
    if (threadIdx.x < D3) bs[threadIdx.x] = b4[threadIdx.x];
    __syncthreads();

    int row = blockIdx.x * blockDim.x + threadIdx.x;
    if (row >= BATCH) return;
    float m = (norms_in[row] > thr_in[0]) ? 1.0f : 0.0f;
    mask_out[row] = m;
    float a[D3];
#pragma unroll
    for (int k = 0; k < D3; k++) a[k] = H3[(size_t)row * D3 + k] * m;
    float ssum = 0.0f;
#pragma unroll
    for (int n = 0; n < D3; n++) {
        float v = bs[n];
#pragma unroll
        for (int k = 0; k < D3; k++) v += a[k] * Ws[k * D3 + n];
        H4[(size_t)row * D3 + n] = v;
        ssum += v * v;
    }
    float nr = sqrtf(ssum);
    norms[row] = nr;
    hist_add(hist, psum, nr);
}

// ---------------- softmax over masked h4 + mask4-out --------------------------
__global__ __launch_bounds__(256)
void softmax_kernel(const float* __restrict__ H4, const float* __restrict__ norms,
                    const float* __restrict__ thr, float* __restrict__ out,
                    float* __restrict__ out_mask) {
    int row = blockIdx.x * blockDim.x + threadIdx.x;
    if (row >= BATCH) return;
    float m = (norms[row] > thr[0]) ? 1.0f : 0.0f;
    out_mask[row] = m;
    float v[D3];
    float mx = -1e30f;
#pragma unroll
    for (int n = 0; n < D3; n++) {
        v[n] = H4[(size_t)row * D3 + n] * m;
        mx = fmaxf(mx, v[n]);
    }
    float s = 0.0f;
#pragma unroll
    for (int n = 0; n < D3; n++) { v[n] = expf(v[n] - mx); s += v[n]; }
    float inv = 1.0f / s;
#pragma unroll
    for (int n = 0; n < D3; n++) out[(size_t)row * D3 + n] = v[n] * inv;
}

// ---------------- launch -----------------------------------------------------
extern "C" void kernel_launch(void* const* d_in, const int* in_sizes, int n_in,
                              void* d_out, int out_size) {
    const float* x  = (const float*)d_in[0];
    const float* W1 = (const float*)d_in[1];
    const float* b1 = (const float*)d_in[2];
    const float* W2 = (const float*)d_in[3];
    const float* b2 = (const float*)d_in[4];
    const float* W3 = (const float*)d_in[5];
    const float* b3 = (const float*)d_in[6];
    const float* W4 = (const float*)d_in[7];
    const float* b4 = (const float*)d_in[8];
    float* out = (float*)d_out;

    float *h1, *h2, *h3, *h4, *nrm, *part, *thr;
    float *w1h, *w1l, *w2h, *w2l;
    unsigned *hist, *psum;
    cudaGetSymbolAddress((void**)&h1, g_h1);
    cudaGetSymbolAddress((void**)&h2, g_h2);
    cudaGetSymbolAddress((void**)&h3, g_h3);
    cudaGetSymbolAddress((void**)&h4, g_h4);
    cudaGetSymbolAddress((void**)&nrm, g_norm);
    cudaGetSymbolAddress((void**)&part, g_part);
    cudaGetSymbolAddress((void**)&thr, g_thr);
    cudaGetSymbolAddress((void**)&w1h, g_w1hT);
    cudaGetSymbolAddress((void**)&w1l, g_w1lT);
    cudaGetSymbolAddress((void**)&w2h, g_w2hT);
    cudaGetSymbolAddress((void**)&w2l, g_w2lT);
    cudaGetSymbolAddress((void**)&hist, g_hist);
    cudaGetSymbolAddress((void**)&psum, g_psum);

    cudaFuncSetAttribute(gemm_tc, cudaFuncAttributeMaxDynamicSharedMemorySize, GEMM_SMEM);

    float* out_m1 = out + (size_t)BATCH * D3;
    float* out_m2 = out_m1 + BATCH;
    float* out_m3 = out_m2 + BATCH;
    float* out_m4 = out_m3 + BATCH;

    unsigned* hist0 = hist;
    unsigned* hist1 = hist + 65536;
    unsigned* hist2 = hist + 2 * 65536;
    unsigned* hist3 = hist + 3 * 65536;
    unsigned* psum0 = psum;
    unsigned* psum1 = psum + 1024;
    unsigned* psum2 = psum + 2 * 1024;
    unsigned* psum3 = psum + 3 * 1024;

    // merged zero + weight split (covers max range D1*KP1 = 409600)
    prep_kernel<<<(D1 * KP1 + 255) / 256, 256>>>(W1, w1h, w1l, W2, w2h, w2l, hist, psum);

    // Layer 1 GEMM: [B,784] -> [B,512]
    {
        const int ntiles = (D1 / TILE_N) * (BATCH / TILE_M);   // 1024
        gemm_tc<<<GRID_P, NTHREADS, GEMM_SMEM>>>(x, w1h, w1l, b1,
                                                 nullptr, nullptr, nullptr,
                                                 h1, part, nullptr, nullptr,
                                                 D0, KP1, KP1 / CHUNK, D1,
                                                 ntiles, D1 / TILE_N);
    }
    combine_kernel<<<BATCH / 256, 256>>>(part, 2, nrm, hist0, psum0);
    select_thr_kernel<<<1, 1024>>>(nrm, hist0, psum0, thr + 0);

    // Layer 2 GEMM: mask1 inline (norms + thr0), writes out_m1, new norms+hist1
    {
        const int ntiles = (D2 / TILE_N) * (BATCH / TILE_M);   // 512
        gemm_tc<<<GRID_P, NTHREADS, GEMM_SMEM>>>(h1, w2h, w2l, b2,
                                                 nrm, thr + 0, out_m1,
                                                 h2, nrm, hist1, psum1,
                                                 D1, KP2, KP2 / CHUNK, D2,
                                                 ntiles, D2 / TILE_N);
    }
    select_thr_kernel<<<1, 1024>>>(nrm, hist1, psum1, thr + 1);

    // Layer 3: mask2 inline, writes out_m2, new norms+hist2
    layer3_kernel<<<(BATCH * 32) / 256, 256>>>(h2, nrm, thr + 1, out_m2,
                                               W3, b3, h3, nrm, hist2, psum2);
    select_thr_kernel<<<1, 1024>>>(nrm, hist2, psum2, thr + 2);

    // Layer 4: mask3 inline, writes out_m3, new norms+hist3
    layer4_kernel<<<BATCH / 256, 256>>>(h3, nrm, thr + 2, out_m3,
                                        W4, b4, h4, nrm, hist3, psum3);
    select_thr_kernel<<<1, 1024>>>(nrm, hist3, psum3, thr + 3);

    // Softmax + mask4 write
    softmax_kernel<<<BATCH / 256, 256>>>(h4, nrm, thr + 3, out, out_m4);
}